// round 10
// baseline (speedup 1.0000x reference)
#include <cuda_runtime.h>
#include <math.h>

#define SLEN 256
#define BATCH 16384
#define HALF_B 8192
#define PI_F 3.14159265358979323846f
#define R2_F 0.70710678118654752440f

typedef unsigned long long ull;

// ---------- packed f32x2 primitives ----------
__device__ __forceinline__ ull F2MUL(ull a, ull b) {
    ull d; asm("mul.rn.f32x2 %0,%1,%2;" : "=l"(d) : "l"(a), "l"(b)); return d;
}
__device__ __forceinline__ ull F2FMA(ull a, ull b, ull c) {
    ull d; asm("fma.rn.f32x2 %0,%1,%2,%3;" : "=l"(d) : "l"(a), "l"(b), "l"(c)); return d;
}
__device__ __forceinline__ ull F2SUB(ull a, ull b) {
    ull d; asm("sub.rn.f32x2 %0,%1,%2;" : "=l"(d) : "l"(a), "l"(b)); return d;
}
__device__ __forceinline__ ull PACK2(float lo, float hi) {
    ull d; asm("mov.b64 %0,{%1,%2};" : "=l"(d) : "f"(lo), "f"(hi)); return d;
}
__device__ __forceinline__ float2 UNPK(ull v) {
    float2 r; asm("mov.b64 {%0,%1},%2;" : "=f"(r.x), "=f"(r.y) : "l"(v)); return r;
}
__device__ __forceinline__ ull SWAPH(ull v) {
    float2 r = UNPK(v); return PACK2(r.y, r.x);
}
__device__ __forceinline__ ull MIXLH(ull a, ull b) {   // (a.lo, b.hi)
    float2 x = UNPK(a), y = UNPK(b); return PACK2(x.x, y.y);
}
__device__ __forceinline__ ull SHFL64(ull v) {
    return __shfl_xor_sync(0xFFFFFFFFu, v, 1);
}

// ---------- precomputed constants (same as round 8/9) ----------
__device__ float2 g_l2a[42];
__device__ float2 g_d1[24];
__device__ float2 g_d2m[24];
__device__ float g_off[32];
__device__ float g_ryf[24];
__device__ float g_kan[119];

__global__ void setup_kernel(const float* __restrict__ p1, const float* __restrict__ p2,
                             const float* __restrict__ base_w, const float* __restrict__ spline_w) {
    int t = threadIdx.x;
    if (t == 0) {
        // ---- L2a: a=0, l=1 rots with H fold ----
        for (int q = 0; q < 4; q++) {
            float phi = p1[12 + q * 3 + 0];
            float th  = p1[12 + q * 3 + 1];
            float om  = p1[12 + q * 3 + 2];
            float st, ct; sincosf(0.5f * th, &st, &ct);
            float sp, cp; sincosf(0.5f * (phi + om), &sp, &cp);
            float sm, cm; sincosf(0.5f * (phi - om), &sm, &cm);
            float ar =  cp * ct, ai = -sp * ct;
            float br = -cm * st, bi = -sm * st;
            float dr =  cm * st, di = -sm * st;
            float er =  cp * ct, ei =  sp * ct;
            float nar = (ar + dr) * R2_F, nai = (ai + di) * R2_F;
            float nbr = (br + er) * R2_F, nbi = (bi + ei) * R2_F;
            float ndr = (ar - dr) * R2_F, ndi = (ai - di) * R2_F;
            float ner = (br - er) * R2_F, nei = (bi - ei) * R2_F;
            ar = nar; ai = nai; br = nbr; bi = nbi;
            dr = ndr; di = ndi; er = ner; ei = nei;
            float2* base = g_l2a;
            if (q == 0) {
                float rows[2][6] = {
                    { ar, -ai, ai, br, -bi, bi },
                    { er, -ei, ei, dr, -di, di }
                };
                for (int p = 0; p < 2; p++) {
                    const float* m = rows[p];
                    float2* o = base + p * 6;
                    o[0] = make_float2(m[0], m[3]);   // A0
                    o[1] = make_float2(m[1], m[4]);   // A1
                    o[2] = make_float2(m[3], m[0]);   // A2
                    o[3] = make_float2(m[4], m[1]);   // A3
                    o[4] = make_float2(m[2], m[5]);   // C2
                    o[5] = make_float2(m[5], m[2]);   // C5
                }
            } else if (q == 1 || q == 2) {
                float2* o = base + (q == 1 ? 12 : 24);
                o[0]  = make_float2(ar, ar);   o[1]  = make_float2(-ai, -ai);
                o[2]  = make_float2(br, br);   o[3]  = make_float2(-bi, -bi);
                o[4]  = make_float2(ai, ai);   o[5]  = make_float2(bi, bi);
                o[6]  = make_float2(dr, dr);   o[7]  = make_float2(-di, -di);
                o[8]  = make_float2(er, er);   o[9]  = make_float2(-ei, -ei);
                o[10] = make_float2(di, di);   o[11] = make_float2(ei, ei);
            } else {
                float2* o = base + 36;
                o[0] = make_float2(ar, er);
                o[1] = make_float2(br, dr);
                o[2] = make_float2(-ai, -ei);
                o[3] = make_float2(-bi, -di);
                o[4] = make_float2(ai, ei);
                o[5] = make_float2(bi, di);
            }
        }
        for (int m = 0; m < 3; m++) {
            int a = (m == 0) ? 0 : 1;
            int l = (m == 2) ? 1 : 0;
            const float* pp = a ? p2 : p1;
            for (int q = 0; q < 4; q++) {
                float th = pp[l * 12 + q * 3 + 1];
                g_ryf[m * 8 + q * 2 + 0] = cosf(0.5f * th);
                g_ryf[m * 8 + q * 2 + 1] = sinf(0.5f * th);
            }
        }
        for (int d = 0; d < 2; d++) {
            const float* pp = d ? p2 : p1;
            float f0 = 0.5f * pp[0], f1 = 0.5f * pp[3], f2 = 0.5f * pp[6], f3 = 0.5f * pp[9];
            for (int s = 0; s < 16; s++) {
                int q0 = (s >> 3) & 1, q1 = (s >> 2) & 1, q2 = (s >> 1) & 1, q3 = s & 1;
                g_off[d * 16 + s] = (q0 ? f0 : -f0) + (q1 ? f1 : -f1)
                                  + (q2 ? f2 : -f2) + (q3 ? f3 : -f3);
            }
        }
        {
            float w0 = 0.5f * p1[2], w1 = 0.5f * p1[5], w2 = 0.5f * p1[8], w3 = 0.5f * p1[11];
            float ph[16];
            for (int s = 0; s < 16; s++) {
                int q0 = (s >> 3) & 1, q1 = (s >> 2) & 1, q2 = (s >> 1) & 1, q3 = s & 1;
                ph[s] = (q0 ? w0 : -w0) + (q1 ? w1 : -w1) + (q2 ? w2 : -w2) + (q3 ? w3 : -w3);
            }
            for (int p = 0; p < 2; p++)
                for (int k = 0; k < 4; k++) {
                    float a0 = ph[p * 8 + k * 2], a1 = ph[p * 8 + k * 2 + 1];
                    g_d1[p * 12 + k]     = make_float2(cosf(a0), cosf(a1));
                    g_d1[p * 12 + 4 + k] = make_float2(sinf(a0), sinf(a1));
                    g_d1[p * 12 + 8 + k] = make_float2(-sinf(a0), -sinf(a1));
                }
        }
        {
            int inv[16];
            for (int s = 0; s < 16; s++) {
                int q0 = (s >> 3) & 1, q1 = (s >> 2) & 1, q2 = (s >> 1) & 1, q3 = s & 1;
                q1 ^= q0; q2 ^= q1; q3 ^= q2; q0 ^= q3;
                inv[(q0 << 3) | (q1 << 2) | (q2 << 1) | q3] = s;
            }
            float f0 = 0.5f * p2[12 + 0], f1 = 0.5f * p2[12 + 3],
                  f2 = 0.5f * p2[12 + 6], f3 = 0.5f * p2[12 + 9];
            float w0 = 0.5f * p2[2], w1 = 0.5f * p2[5],
                  w2 = 0.5f * p2[8], w3 = 0.5f * p2[11];
            float ph[16];
            for (int j = 0; j < 16; j++) {
                int q0 = (j >> 3) & 1, q1 = (j >> 2) & 1, q2 = (j >> 1) & 1, q3 = j & 1;
                int i = inv[j];
                int r0 = (i >> 3) & 1, r1 = (i >> 2) & 1, r2 = (i >> 1) & 1, r3 = i & 1;
                ph[j] = (q0 ? f0 : -f0) + (q1 ? f1 : -f1) + (q2 ? f2 : -f2) + (q3 ? f3 : -f3)
                      + (r0 ? w0 : -w0) + (r1 ? w1 : -w1) + (r2 ? w2 : -w2) + (r3 ? w3 : -w3);
            }
            for (int p = 0; p < 2; p++)
                for (int k = 0; k < 4; k++) {
                    float a0 = ph[p * 8 + k * 2], a1 = ph[(1 - p) * 8 + k * 2 + 1];
                    g_d2m[p * 12 + k]     = make_float2(cosf(a0), cosf(a1));
                    g_d2m[p * 12 + 4 + k] = make_float2(sinf(a0), sinf(a1));
                    g_d2m[p * 12 + 8 + k] = make_float2(-sinf(a0), -sinf(a1));
                }
        }
    }
    if (t == 1) {
        const float BP[4][4] = {
            {1.f, -3.f, 3.f, -1.f},
            {23.f, -15.f, -3.f, 3.f},
            {23.f, 15.f, -3.f, -3.f},
            {1.f, 3.f, 3.f, 1.f}
        };
        const float inv48 = 1.0f / 48.0f;
        for (int o = 0; o < 7; o++) {
            float c0sum = 0.f;
            for (int in = 0; in < 4; in++) {
                float P[4] = {0.f, 0.f, 0.f, 0.f};
                for (int j = 0; j < 4; j++) {
                    float w = spline_w[o * 16 + in * 4 + j] * inv48;
                    for (int k = 0; k < 4; k++) P[k] += w * BP[j][k];
                }
                g_kan[o * 17 + in]      = base_w[o * 4 + in];
                g_kan[o * 17 + 4 + in]  = P[1];
                g_kan[o * 17 + 8 + in]  = P[2];
                g_kan[o * 17 + 12 + in] = P[3];
                c0sum += P[0];
            }
            g_kan[o * 17 + 16] = c0sum;
        }
    }
}

// ---------------- dual-element split-state gates ----------------
// Each thread: TWO elements. State R[8],I[8]: regs 0-3 = elem A, 4-7 = elem B.
// Within each half: thread bit p = q0; reg bit1=q1, bit0=q2; f32x2 lane = q3.
// "Mixed" rep after a skipped HIXCH: own reg = (true_p.lo, true_{1-p}.hi).

struct RYC {
    ull D0, D1;
    ull cc1, ss1, ns1;
    ull cc2, ss2, ns2;
    ull cc3, sm3;
};

struct L2AC {
    ull a0, a1, a2, a3, c2, c5;
    ull t0, t1, t2, t3, t4, t5;
};

__device__ __forceinline__ void ry8(ull* R, ull* I, const RYC& c) {
    // q0 (thread axis), both halves
    {
#pragma unroll
        for (int k = 0; k < 8; k++) {
            ull PR = SHFL64(R[k]);
            R[k] = F2FMA(c.D1, PR, F2MUL(c.D0, R[k]));
        }
#pragma unroll
        for (int k = 0; k < 8; k++) {
            ull PI = SHFL64(I[k]);
            I[k] = F2FMA(c.D1, PI, F2MUL(c.D0, I[k]));
        }
    }
    // q1: pairs (h+0,h+2),(h+1,h+3) for h in {0,4}
#pragma unroll
    for (int h = 0; h < 8; h += 4) {
        ull a, b;
        a = R[h + 0]; b = R[h + 2]; R[h + 0] = F2FMA(c.ns1, b, F2MUL(c.cc1, a)); R[h + 2] = F2FMA(c.ss1, a, F2MUL(c.cc1, b));
        a = R[h + 1]; b = R[h + 3]; R[h + 1] = F2FMA(c.ns1, b, F2MUL(c.cc1, a)); R[h + 3] = F2FMA(c.ss1, a, F2MUL(c.cc1, b));
        a = I[h + 0]; b = I[h + 2]; I[h + 0] = F2FMA(c.ns1, b, F2MUL(c.cc1, a)); I[h + 2] = F2FMA(c.ss1, a, F2MUL(c.cc1, b));
        a = I[h + 1]; b = I[h + 3]; I[h + 1] = F2FMA(c.ns1, b, F2MUL(c.cc1, a)); I[h + 3] = F2FMA(c.ss1, a, F2MUL(c.cc1, b));
    }
    // q2: pairs (k,k+1), k even
#pragma unroll
    for (int k = 0; k < 8; k += 2) {
        ull a, b;
        a = R[k]; b = R[k + 1]; R[k] = F2FMA(c.ns2, b, F2MUL(c.cc2, a)); R[k + 1] = F2FMA(c.ss2, a, F2MUL(c.cc2, b));
        a = I[k]; b = I[k + 1]; I[k] = F2FMA(c.ns2, b, F2MUL(c.cc2, a)); I[k + 1] = F2FMA(c.ss2, a, F2MUL(c.cc2, b));
    }
    // q3 (lane axis)
#pragma unroll
    for (int k = 0; k < 8; k++) {
        ull v = R[k]; R[k] = F2FMA(c.sm3, SWAPH(v), F2MUL(c.cc3, v));
        ull w = I[k]; I[k] = F2FMA(c.sm3, SWAPH(w), F2MUL(c.cc3, w));
    }
}

__device__ __forceinline__ void diag8(ull* R, ull* I, const ull* d) {
#pragma unroll
    for (int k = 0; k < 8; k++) {
        ull C = d[k & 3], S = d[4 + (k & 3)], nS = d[8 + (k & 3)];
        ull r = R[k], im = I[k];
        R[k] = F2FMA(nS, im, F2MUL(C, r));
        I[k] = F2FMA(S, r, F2MUL(C, im));
    }
}

__device__ __forceinline__ void layer_l2a8(ull* R, ull* I, const ull* sq12, const L2AC& C) {
    // rot q0 (fused, premixed): input mixed, output TRUE
    {
#pragma unroll
        for (int k = 0; k < 8; k++) {
            ull YR = SHFL64(R[k]), YI = SHFL64(I[k]);
            ull xr = R[k], xi = I[k];
            ull t = F2MUL(C.a0, xr); t = F2FMA(C.a1, xi, t); t = F2FMA(C.a2, YR, t); t = F2FMA(C.a3, YI, t);
            ull u = F2MUL(C.a0, xi); u = F2FMA(C.c2, xr, u); u = F2FMA(C.a2, YI, u); u = F2FMA(C.c5, YR, u);
            R[k] = t; I[k] = u;
        }
    }
    // rot q1: pairs (h+k, h+k+2)
    {
        const ulonglong2* v = reinterpret_cast<const ulonglong2*>(sq12);
        ulonglong2 v0 = v[0], v1 = v[1], v2 = v[2], v3 = v[3], v4 = v[4], v5 = v[5];
#pragma unroll
        for (int h = 0; h < 8; h += 4) {
#pragma unroll
            for (int k = 0; k < 2; k++) {
                const int i0 = h + k, j = h + k + 2;
                ull x0r = R[i0], x0i = I[i0], x1r = R[j], x1i = I[j];
                ull t;
                t = F2MUL(v0.x, x0r); t = F2FMA(v0.y, x0i, t); t = F2FMA(v1.x, x1r, t); t = F2FMA(v1.y, x1i, t); R[i0] = t;
                t = F2MUL(v0.x, x0i); t = F2FMA(v2.x, x0r, t); t = F2FMA(v1.x, x1i, t); t = F2FMA(v2.y, x1r, t); I[i0] = t;
                t = F2MUL(v3.x, x0r); t = F2FMA(v3.y, x0i, t); t = F2FMA(v4.x, x1r, t); t = F2FMA(v4.y, x1i, t); R[j] = t;
                t = F2MUL(v3.x, x0i); t = F2FMA(v5.x, x0r, t); t = F2FMA(v4.x, x1i, t); t = F2FMA(v5.y, x1r, t); I[j] = t;
            }
        }
    }
    // rot q2: pairs (k, k+1), k even
    {
        const ulonglong2* v = reinterpret_cast<const ulonglong2*>(sq12 + 12);
        ulonglong2 v0 = v[0], v1 = v[1], v2 = v[2], v3 = v[3], v4 = v[4], v5 = v[5];
#pragma unroll
        for (int k = 0; k < 8; k += 2) {
            const int j = k + 1;
            ull x0r = R[k], x0i = I[k], x1r = R[j], x1i = I[j];
            ull t;
            t = F2MUL(v0.x, x0r); t = F2FMA(v0.y, x0i, t); t = F2FMA(v1.x, x1r, t); t = F2FMA(v1.y, x1i, t); R[k] = t;
            t = F2MUL(v0.x, x0i); t = F2FMA(v2.x, x0r, t); t = F2FMA(v1.x, x1i, t); t = F2FMA(v2.y, x1r, t); I[k] = t;
            t = F2MUL(v3.x, x0r); t = F2FMA(v3.y, x0i, t); t = F2FMA(v4.x, x1r, t); t = F2FMA(v4.y, x1i, t); R[j] = t;
            t = F2MUL(v3.x, x0i); t = F2FMA(v5.x, x0r, t); t = F2FMA(v4.x, x1i, t); t = F2FMA(v5.y, x1r, t); I[j] = t;
        }
    }
    // rot q3 (lane axis)
#pragma unroll
    for (int k = 0; k < 8; k++) {
        ull pr = R[k], pi = I[k];
        ull prs = SWAPH(pr), pis = SWAPH(pi);
        ull t = F2MUL(C.t0, pr); t = F2FMA(C.t1, prs, t); t = F2FMA(C.t2, pi, t); t = F2FMA(C.t3, pis, t);
        ull u = F2MUL(C.t4, pr); u = F2FMA(C.t5, prs, u); u = F2FMA(C.t0, pi, u); u = F2FMA(C.t1, pis, u);
        R[k] = t; I[k] = u;
    }
}

// ring without final HIXCH (per half)
__device__ __forceinline__ void ring_nox8(ull* R, ull* I, int p) {
#pragma unroll
    for (int h = 0; h < 8; h += 4) {
        {
            ull r0 = R[h], r1 = R[h + 1], r2 = R[h + 2], r3 = R[h + 3];
            R[h] = p ? r2 : r0; R[h + 2] = p ? r0 : r2;
            R[h + 1] = p ? r3 : r1; R[h + 3] = p ? r1 : r3;
            ull i0 = I[h], i1 = I[h + 1], i2 = I[h + 2], i3 = I[h + 3];
            I[h] = p ? i2 : i0; I[h + 2] = p ? i0 : i2;
            I[h + 1] = p ? i3 : i1; I[h + 3] = p ? i1 : i3;
        }
        { ull t = R[h + 2]; R[h + 2] = R[h + 3]; R[h + 3] = t;
          t = I[h + 2]; I[h + 2] = I[h + 3]; I[h + 3] = t; }
        R[h + 1] = SWAPH(R[h + 1]); R[h + 3] = SWAPH(R[h + 3]);
        I[h + 1] = SWAPH(I[h + 1]); I[h + 3] = SWAPH(I[h + 3]);
    }
}

// reversed ring (per half)
__device__ __forceinline__ void ring_rev8(ull* R, ull* I, int p) {
#pragma unroll
    for (int h = 0; h < 8; h += 4) {
        R[h + 2] = SHFL64(R[h + 2]); R[h + 3] = SHFL64(R[h + 3]);
        I[h + 2] = SHFL64(I[h + 2]); I[h + 3] = SHFL64(I[h + 3]);
        { ull t = R[h + 1]; R[h + 1] = R[h + 3]; R[h + 3] = t;
          t = I[h + 1]; I[h + 1] = I[h + 3]; I[h + 3] = t; }
        {
            ull a = R[h], b = R[h + 1]; R[h] = MIXLH(a, b); R[h + 1] = MIXLH(b, a);
            ull c = R[h + 2], d = R[h + 3]; R[h + 2] = MIXLH(c, d); R[h + 3] = MIXLH(d, c);
            ull e = I[h], f = I[h + 1]; I[h] = MIXLH(e, f); I[h + 1] = MIXLH(f, e);
            ull g = I[h + 2], x = I[h + 3]; I[h + 2] = MIXLH(g, x); I[h + 3] = MIXLH(x, g);
        }
#pragma unroll
        for (int k = 0; k < 4; k++) {
            R[h + k] = p ? SWAPH(R[h + k]) : R[h + k];
            I[h + k] = p ? SWAPH(I[h + k]) : I[h + k];
        }
    }
}

__device__ __forceinline__ void phases8(const float* ang, int p, float* ph) {
    float b0 = 0.5f * ang[0], b1 = 0.5f * ang[1], b2 = 0.5f * ang[2], b3 = 0.5f * ang[3];
    float b4 = 0.5f * ang[4], b5 = 0.5f * ang[5], b6 = 0.5f * ang[6];
    float t01 = b0 + b1, d01 = b0 - b1;
    float uA = p ? (d01 + b4) : (-t01 - b4);
    float uB = p ? (t01 - b4) : (-d01 + b4);
    float t23 = b2 + b3, d23 = b2 - b3;
    float e00 = -t23 - b6, e01 = -d23 + b6, e10 = d23 + b6, e11 = t23 - b6;
    ph[0] = uA + (e00 - b5); ph[1] = uA + (e01 - b5);
    ph[2] = uA + (e10 + b5); ph[3] = uA + (e11 + b5);
    ph[4] = uB + (e00 + b5); ph[5] = uB + (e01 + b5);
    ph[6] = uB + (e10 - b5); ph[7] = uB + (e11 - b5);
}

__device__ __forceinline__ void d_init4(ull* R, ull* I, const float* ph, const float* off) {
#pragma unroll
    for (int k = 0; k < 4; k++) {
        float s0, c0, s1, c1;
        __sincosf(ph[2 * k] + off[2 * k], &s0, &c0);
        __sincosf(ph[2 * k + 1] + off[2 * k + 1], &s1, &c1);
        R[k] = PACK2(c0, c1); I[k] = PACK2(s0, s1);
    }
}

__device__ __forceinline__ void d_cmul4(ull* R, ull* I, const float* ph, const float* off) {
#pragma unroll
    for (int k = 0; k < 4; k++) {
        float s0, c0, s1, c1;
        __sincosf(ph[2 * k] + off[2 * k], &s0, &c0);
        __sincosf(ph[2 * k + 1] + off[2 * k + 1], &s1, &c1);
        ull c = PACK2(c0, c1), s = PACK2(s0, s1);
        ull nr = F2SUB(F2MUL(c, R[k]), F2MUL(s, I[k]));
        I[k] = F2FMA(s, R[k], F2MUL(c, I[k]));
        R[k] = nr;
    }
}

__device__ __forceinline__ void measure4(const ull* R, const ull* I,
                                         float sgnp, float* ev) {
    float sv[4], dv[4];
#pragma unroll
    for (int k = 0; k < 4; k++) {
        ull P = F2FMA(I[k], I[k], F2MUL(R[k], R[k]));
        float2 f = UNPK(P);
        sv[k] = f.x + f.y;
        dv[k] = f.x - f.y;
    }
    float A = dv[0] - dv[1] - dv[2] + dv[3];
    float C = sv[0] + sv[1] - sv[2] - sv[3];
    float D = sv[0] - sv[1] - sv[2] + sv[3];
    float Ax = __shfl_xor_sync(0xFFFFFFFFu, A, 1);
    float Cx = __shfl_xor_sync(0xFFFFFFFFu, C, 1);
    float Dx = __shfl_xor_sync(0xFFFFFFFFu, D, 1);
    const float sc = 1.0f / 16.0f;
    ev[0] = (A + Ax) * sc;
    ev[1] = sgnp * (C - Cx) * sc;
    ev[2] = sgnp * (D - Dx) * sc;
    ev[3] = sgnp * (A - Ax) * sc;
}

// Cooperative KAN [round-9 verified]
__device__ __forceinline__ void kan_coop(const float* hid, const float* W, int p,
                                         float* oang) {
    float sl[4], x2[4], x3[4];
#pragma unroll
    for (int in = 0; in < 4; in++) {
        float x = hid[in];
        float e = __expf(-x);
        sl[in] = __fdividef(x, 1.0f + e);
        x2[in] = x * x;
        x3[in] = x2[in] * x;
    }
    float r[4];
#pragma unroll
    for (int j = 0; j < 4; j++) {
        const float* w = W + j * 17;
        float acc = w[16];
#pragma unroll
        for (int in = 0; in < 4; in++) acc = fmaf(w[in], sl[in], acc);
#pragma unroll
        for (int in = 0; in < 4; in++) acc = fmaf(w[4 + in], hid[in], acc);
#pragma unroll
        for (int in = 0; in < 4; in++) acc = fmaf(w[8 + in], x2[in], acc);
#pragma unroll
        for (int in = 0; in < 4; in++) acc = fmaf(w[12 + in], x3[in], acc);
        r[j] = acc;
    }
    float s0 = __shfl_xor_sync(0xFFFFFFFFu, r[0], 1);
    float s1 = __shfl_xor_sync(0xFFFFFFFFu, r[1], 1);
    float s2 = __shfl_xor_sync(0xFFFFFFFFu, r[2], 1);
    float s3 = __shfl_xor_sync(0xFFFFFFFFu, r[3], 1);
    oang[0] = p ? s0 : r[0];
    oang[1] = p ? s1 : r[1];
    oang[2] = p ? s2 : r[2];
    oang[3] = p ? r[0] : r[3];
    oang[4] = p ? r[1] : s1;
    oang[5] = p ? r[2] : s2;
    oang[6] = p ? r[3] : s3;
}

__global__ void __launch_bounds__(128, 1) qrnn_kernel(
    const float* __restrict__ inputs,      // [B, S, 4]
    const float* __restrict__ initial_t,   // [B, 7]
    const float* __restrict__ cw1,         // [16, 4]
    const float* __restrict__ cb1,         // [16]
    const float* __restrict__ cw2,         // [1, 16]
    const float* __restrict__ cb2,         // [1]
    float* __restrict__ out)               // [B]
{
    __shared__ __align__(16) ull s_q12[24];
    __shared__ __align__(16) ull s_d1[24];
    __shared__ __align__(16) ull s_d2[24];
    __shared__ float s_kanb[136];
    int tid = threadIdx.x;
    {
        const ull* a = reinterpret_cast<const ull*>(g_l2a);
        const ull* b = reinterpret_cast<const ull*>(g_d1);
        const ull* c = reinterpret_cast<const ull*>(g_d2m);
        if (tid < 24) s_q12[tid] = a[12 + tid];
        if (tid >= 24 && tid < 48) s_d1[tid - 24] = b[tid - 24];
        if (tid >= 48 && tid < 72) s_d2[tid - 48] = c[tid - 48];
        for (int i = tid; i < 136; i += 128) {
            int bnk = i / 68, rem = i % 68;
            int j = rem / 17, k = rem % 17;
            int o = bnk ? (3 + j) : j;
            s_kanb[i] = g_kan[o * 17 + k];
        }
    }
    __syncthreads();

    int gtid = blockIdx.x * blockDim.x + tid;
    int eA = gtid >> 1;            // element A
    int eB = eA + HALF_B;          // element B
    int p = gtid & 1;
    float sgnp = p ? -1.0f : 1.0f;
    const float* kanW = s_kanb + p * 68;
    const ull* d1 = s_d1 + p * 12;
    const ull* d2 = s_d2 + p * 12;

    float off1[8], off2[8];
#pragma unroll
    for (int s = 0; s < 8; s++) {
        off1[s] = g_off[p * 8 + s];
        off2[s] = g_off[16 + p * 8 + s];
    }
    RYC ry[3];
#pragma unroll
    for (int m = 0; m < 3; m++) {
        float c0 = g_ryf[m * 8 + 0], s0 = g_ryf[m * 8 + 1];
        float c1 = g_ryf[m * 8 + 2], s1 = g_ryf[m * 8 + 3];
        float c2 = g_ryf[m * 8 + 4], s2 = g_ryf[m * 8 + 5];
        float c3 = g_ryf[m * 8 + 6], s3 = g_ryf[m * 8 + 7];
        float s0p = p ? s0 : -s0;
        if (m == 2) {
            ry[m].D0 = PACK2(c0, s0p); ry[m].D1 = PACK2(s0p, c0);
        } else {
            ry[m].D0 = PACK2(c0, c0);  ry[m].D1 = PACK2(s0p, s0p);
        }
        ry[m].cc1 = PACK2(c1, c1); ry[m].ss1 = PACK2(s1, s1); ry[m].ns1 = PACK2(-s1, -s1);
        ry[m].cc2 = PACK2(c2, c2); ry[m].ss2 = PACK2(s2, s2); ry[m].ns2 = PACK2(-s2, -s2);
        ry[m].cc3 = PACK2(c3, c3); ry[m].sm3 = PACK2(-s3, s3);
    }
    L2AC l2c;
    {
        const ull* a = reinterpret_cast<const ull*>(g_l2a);
        const ull* mq = a + p * 6;
        l2c.a0 = mq[0]; l2c.a1 = mq[1]; l2c.a2 = mq[2];
        l2c.a3 = mq[3]; l2c.c2 = mq[4]; l2c.c5 = mq[5];
        l2c.t0 = a[36]; l2c.t1 = a[37]; l2c.t2 = a[38];
        l2c.t3 = a[39]; l2c.t4 = a[40]; l2c.t5 = a[41];
    }

    float hA[7], hB[7];
#pragma unroll
    for (int k = 0; k < 7; k++) {
        hA[k] = initial_t[eA * 7 + k];
        hB[k] = initial_t[eB * 7 + k];
    }

    const float4* inA = reinterpret_cast<const float4*>(inputs) + (size_t)eA * SLEN;
    const float4* inB = reinterpret_cast<const float4*>(inputs) + (size_t)eB * SLEN;

    float hidA[4], hidB[4];
#pragma unroll 1
    for (int t = 0; t < SLEN; t++) {
        float4 xa = inA[t], xb = inB[t];
        float xangA[7], xangB[7];
        xangA[0] = xa.x; xangA[1] = xa.y; xangA[2] = xa.z; xangA[3] = xa.w;
        xangA[4] = (PI_F - xa.x) * (PI_F - xa.y);
        xangA[5] = (PI_F - xa.y) * (PI_F - xa.z);
        xangA[6] = (PI_F - xa.z) * (PI_F - xa.w);
        xangB[0] = xb.x; xangB[1] = xb.y; xangB[2] = xb.z; xangB[3] = xb.w;
        xangB[4] = (PI_F - xb.x) * (PI_F - xb.y);
        xangB[5] = (PI_F - xb.y) * (PI_F - xb.z);
        xangB[6] = (PI_F - xb.z) * (PI_F - xb.w);
        if (t > 0) {
            kan_coop(hidA, kanW, p, hA);
            kan_coop(hidB, kanW, p, hB);
        }

        ull R[8], I[8];
        float ph[8];
        // D1
        phases8(hA, p, ph); d_init4(R, I, ph, off1);
        phases8(hB, p, ph); d_init4(R + 4, I + 4, ph, off1);
        // ansatz 1
        ry8(R, I, ry[0]);
        diag8(R, I, d1);
        ring_nox8(R, I, p);
        layer_l2a8(R, I, s_q12, l2c);
        ring_rev8(R, I, p);
        // D2
        phases8(xangA, p, ph); d_cmul4(R, I, ph, off2);
        phases8(xangB, p, ph); d_cmul4(R + 4, I + 4, ph, off2);
        // ansatz 2
        ry8(R, I, ry[1]);
        ring_nox8(R, I, p);
        diag8(R, I, d2);
        ry8(R, I, ry[2]);
        // measurement
        measure4(R, I, sgnp, hidA);
        measure4(R + 4, I + 4, sgnp, hidB);
    }

    float oA = cb2[0], oB = cb2[0];
#pragma unroll 1
    for (int k = 0; k < 16; k++) {
        float w0 = cw1[k * 4 + 0], w1 = cw1[k * 4 + 1];
        float w2 = cw1[k * 4 + 2], w3 = cw1[k * 4 + 3];
        float b = cb1[k], v = cw2[k];
        float a = b;
        a = fmaf(w0, hidA[0], a); a = fmaf(w1, hidA[1], a);
        a = fmaf(w2, hidA[2], a); a = fmaf(w3, hidA[3], a);
        oA = fmaf(v, fmaxf(a, 0.0f), oA);
        float c = b;
        c = fmaf(w0, hidB[0], c); c = fmaf(w1, hidB[1], c);
        c = fmaf(w2, hidB[2], c); c = fmaf(w3, hidB[3], c);
        oB = fmaf(v, fmaxf(c, 0.0f), oB);
    }
    if (p == 0) {
        out[eA] = oA;
        out[eB] = oB;
    }
}

extern "C" void kernel_launch(void* const* d_in, const int* in_sizes, int n_in,
                              void* d_out, int out_size) {
    const float* inputs    = (const float*)d_in[0];
    const float* initial_t = (const float*)d_in[1];
    const float* p1        = (const float*)d_in[2];
    const float* p2        = (const float*)d_in[3];
    const float* base_w    = (const float*)d_in[4];
    const float* spline_w  = (const float*)d_in[5];
    const float* cw1       = (const float*)d_in[6];
    const float* cb1       = (const float*)d_in[7];
    const float* cw2       = (const float*)d_in[8];
    const float* cb2       = (const float*)d_in[9];

    setup_kernel<<<1, 32>>>(p1, p2, base_w, spline_w);
    qrnn_kernel<<<BATCH / 128, 128>>>(inputs, initial_t,
                                      cw1, cb1, cw2, cb2, (float*)d_out);
}

// round 11
// speedup vs baseline: 1.0588x; 1.0588x over previous
#include <cuda_runtime.h>
#include <math.h>

#define SLEN 256
#define BATCH 16384
#define PI_F 3.14159265358979323846f
#define R2_F 0.70710678118654752440f

typedef unsigned long long ull;

// ---------- packed f32x2 primitives ----------
__device__ __forceinline__ ull F2MUL(ull a, ull b) {
    ull d; asm("mul.rn.f32x2 %0,%1,%2;" : "=l"(d) : "l"(a), "l"(b)); return d;
}
__device__ __forceinline__ ull F2FMA(ull a, ull b, ull c) {
    ull d; asm("fma.rn.f32x2 %0,%1,%2,%3;" : "=l"(d) : "l"(a), "l"(b), "l"(c)); return d;
}
__device__ __forceinline__ ull F2SUB(ull a, ull b) {
    ull d; asm("sub.rn.f32x2 %0,%1,%2;" : "=l"(d) : "l"(a), "l"(b)); return d;
}
__device__ __forceinline__ ull PACK2(float lo, float hi) {
    ull d; asm("mov.b64 %0,{%1,%2};" : "=l"(d) : "f"(lo), "f"(hi)); return d;
}
__device__ __forceinline__ float2 UNPK(ull v) {
    float2 r; asm("mov.b64 {%0,%1},%2;" : "=f"(r.x), "=f"(r.y) : "l"(v)); return r;
}
__device__ __forceinline__ ull SWAPH(ull v) {
    float2 r = UNPK(v); return PACK2(r.y, r.x);
}
__device__ __forceinline__ ull MIXLH(ull a, ull b) {   // (a.lo, b.hi)
    float2 x = UNPK(a), y = UNPK(b); return PACK2(x.x, y.y);
}
__device__ __forceinline__ ull SHFL64(ull v) {
    return __shfl_xor_sync(0xFFFFFFFFu, v, 1);
}

// ---------- precomputed constants ----------
// d1: plain diag (omega_1a + RZ(C_l2a) pushed back through ring): [p][C|S|nS]
__device__ float2 g_d1[24];
// d2m: PREMIXED diag (omega1b through ring * phi2b): lo lane p, hi lane 1-p
__device__ float2 g_d2m[24];
// phase offsets: [diag 0/1][slot s=q0*8+q1*4+q2*2+q3]
// diag1 additionally contains RZ(A_l2a) pushed forward through ring_rev
__device__ float g_off[32];
// RY coefs: [layer m=0(1a),1(1b),2(2b),3(l2a ZYZ)][q][c,s]
__device__ float g_ryf[32];
// KAN folded weights: 7 outputs x 20 (base[4], c1[4], c2[4], c3[4], c0sum, pad)
__device__ float g_kan[140];

__global__ void setup_kernel(const float* __restrict__ p1, const float* __restrict__ p2,
                             const float* __restrict__ base_w, const float* __restrict__ spline_w) {
    int t = threadIdx.x;
    if (t == 0) {
        // ---- l2a = H * Rot(a=0,l=1) per qubit; ZYZ extract A,B,C ----
        double Aq[4], Cq[4];
        for (int q = 0; q < 4; q++) {
            float phi = p1[12 + q * 3 + 0];
            float th  = p1[12 + q * 3 + 1];
            float om  = p1[12 + q * 3 + 2];
            float st, ct; sincosf(0.5f * th, &st, &ct);
            float sp, cp; sincosf(0.5f * (phi + om), &sp, &cp);
            float sm, cm; sincosf(0.5f * (phi - om), &sm, &cm);
            double ar =  (double)cp * ct, ai = -(double)sp * ct;
            double br = -(double)cm * st, bi = -(double)sm * st;
            double dr =  (double)cm * st, di = -(double)sm * st;
            double er =  (double)cp * ct, ei =  (double)sp * ct;
            // U = H @ Rot
            const double r2 = 0.70710678118654752440;
            double u00r = (ar + dr) * r2, u00i = (ai + di) * r2;
            double u01r = (br + er) * r2, u01i = (bi + ei) * r2;
            double u10r = (ar - dr) * r2, u10i = (ai - di) * r2;
            double u11r = (br - er) * r2, u11i = (bi - ei) * r2;
            // det = u00*u11 - u01*u10
            double detr = u00r * u11r - u00i * u11i - (u01r * u10r - u01i * u10i);
            double deti = u00r * u11i + u00i * u11r - (u01r * u10i + u01i * u10r);
            double alpha = 0.5 * atan2(deti, detr);
            double ca = cos(-alpha), sa = sin(-alpha);
            // v = U * e^{-i alpha}
            double v00r = u00r * ca - u00i * sa, v00i = u00r * sa + u00i * ca;
            double v10r = u10r * ca - u10i * sa, v10i = u10r * sa + u10i * ca;
            double cB = sqrt(v00r * v00r + v00i * v00i);
            double sB = sqrt(v10r * v10r + v10i * v10i);
            double a00 = (cB > 1e-12) ? atan2(v00i, v00r) : 0.0;
            double a10 = (sB > 1e-12) ? atan2(v10i, v10r) : 0.0;
            double ApC = -2.0 * a00;
            double AmC =  2.0 * a10;
            Aq[q] = 0.5 * (ApC + AmC);
            Cq[q] = 0.5 * (ApC - AmC);
            // RY(B) coefficients (cos(B/2)=cB, sin(B/2)=sB, both >= 0)
            g_ryf[24 + q * 2 + 0] = (float)cB;
            g_ryf[24 + q * 2 + 1] = (float)sB;
        }
        // ---- RY coefficients for layers 1a(a0l0), 1b(a1l0), 2b(a1l1) ----
        for (int m = 0; m < 3; m++) {
            int a = (m == 0) ? 0 : 1;
            int l = (m == 2) ? 1 : 0;
            const float* pp = a ? p2 : p1;
            for (int q = 0; q < 4; q++) {
                float th = pp[l * 12 + q * 3 + 1];
                g_ryf[m * 8 + q * 2 + 0] = cosf(0.5f * th);
                g_ryf[m * 8 + q * 2 + 1] = sinf(0.5f * th);
            }
        }
        // ---- phase tables for RZ(C) and RZ(A) of l2a ----
        double phC[16], phA[16];
        for (int s = 0; s < 16; s++) {
            int b0 = (s >> 3) & 1, b1 = (s >> 2) & 1, b2 = (s >> 1) & 1, b3 = s & 1;
            phC[s] = (b0 ? 0.5 : -0.5) * Cq[0] + (b1 ? 0.5 : -0.5) * Cq[1]
                   + (b2 ? 0.5 : -0.5) * Cq[2] + (b3 ? 0.5 : -0.5) * Cq[3];
            phA[s] = (b0 ? 0.5 : -0.5) * Aq[0] + (b1 ? 0.5 : -0.5) * Aq[1]
                   + (b2 ? 0.5 : -0.5) * Aq[2] + (b3 ? 0.5 : -0.5) * Aq[3];
        }
        // forward sequential map of ring_normal: M(s)
        int Mn[16];
        for (int s = 0; s < 16; s++) {
            int q0 = (s >> 3) & 1, q1 = (s >> 2) & 1, q2 = (s >> 1) & 1, q3 = s & 1;
            q1 ^= q0; q2 ^= q1; q3 ^= q2; q0 ^= q3;
            Mn[s] = (q0 << 3) | (q1 << 2) | (q2 << 1) | q3;
        }
        // forward sequential map of ring_rev and its inverse
        int rinv[16];
        for (int s = 0; s < 16; s++) {
            int q0 = (s >> 3) & 1, q1 = (s >> 2) & 1, q2 = (s >> 1) & 1, q3 = s & 1;
            q0 ^= q1; q1 ^= q2; q2 ^= q3; q3 ^= q0;
            rinv[(q0 << 3) | (q1 << 2) | (q2 << 1) | q3] = s;
        }
        // ---- phase offsets: Dphi(1a) -> off slot 0; Dphi(1b) + RZ(A)∘rinv -> slot 1 ----
        for (int d = 0; d < 2; d++) {
            const float* pp = d ? p2 : p1;
            float f0 = 0.5f * pp[0], f1 = 0.5f * pp[3], f2 = 0.5f * pp[6], f3 = 0.5f * pp[9];
            for (int s = 0; s < 16; s++) {
                int q0 = (s >> 3) & 1, q1 = (s >> 2) & 1, q2 = (s >> 1) & 1, q3 = s & 1;
                float v = (q0 ? f0 : -f0) + (q1 ? f1 : -f1)
                        + (q2 ? f2 : -f2) + (q3 ? f3 : -f3);
                if (d == 1) v += (float)phA[rinv[s]];
                g_off[d * 16 + s] = v;
            }
        }
        // ---- d1: Domega(1a) * RZ(C_l2a)∘M ----
        {
            float w0 = 0.5f * p1[2], w1 = 0.5f * p1[5], w2 = 0.5f * p1[8], w3 = 0.5f * p1[11];
            float ph[16];
            for (int s = 0; s < 16; s++) {
                int q0 = (s >> 3) & 1, q1 = (s >> 2) & 1, q2 = (s >> 1) & 1, q3 = s & 1;
                ph[s] = (q0 ? w0 : -w0) + (q1 ? w1 : -w1) + (q2 ? w2 : -w2) + (q3 ? w3 : -w3)
                      + (float)phC[Mn[s]];
            }
            for (int p = 0; p < 2; p++)
                for (int k = 0; k < 4; k++) {
                    float a0 = ph[p * 8 + k * 2], a1 = ph[p * 8 + k * 2 + 1];
                    g_d1[p * 12 + k]     = make_float2(cosf(a0), cosf(a1));
                    g_d1[p * 12 + 4 + k] = make_float2(sinf(a0), sinf(a1));
                    g_d1[p * 12 + 8 + k] = make_float2(-sinf(a0), -sinf(a1));
                }
        }
        // ---- d2m: Domega(1b) through ring * Dphi(2b), hi-lane PREMIXED across p ----
        {
            int inv[16];
            for (int s = 0; s < 16; s++) {
                int q0 = (s >> 3) & 1, q1 = (s >> 2) & 1, q2 = (s >> 1) & 1, q3 = s & 1;
                q1 ^= q0; q2 ^= q1; q3 ^= q2; q0 ^= q3;
                inv[(q0 << 3) | (q1 << 2) | (q2 << 1) | q3] = s;
            }
            float f0 = 0.5f * p2[12 + 0], f1 = 0.5f * p2[12 + 3],
                  f2 = 0.5f * p2[12 + 6], f3 = 0.5f * p2[12 + 9];   // phi of 2b
            float w0 = 0.5f * p2[2], w1 = 0.5f * p2[5],
                  w2 = 0.5f * p2[8], w3 = 0.5f * p2[11];            // omega of 1b
            float ph[16];
            for (int j = 0; j < 16; j++) {
                int q0 = (j >> 3) & 1, q1 = (j >> 2) & 1, q2 = (j >> 1) & 1, q3 = j & 1;
                int i = inv[j];
                int r0 = (i >> 3) & 1, r1 = (i >> 2) & 1, r2 = (i >> 1) & 1, r3 = i & 1;
                ph[j] = (q0 ? f0 : -f0) + (q1 ? f1 : -f1) + (q2 ? f2 : -f2) + (q3 ? f3 : -f3)
                      + (r0 ? w0 : -w0) + (r1 ? w1 : -w1) + (r2 ? w2 : -w2) + (r3 ? w3 : -w3);
            }
            for (int p = 0; p < 2; p++)
                for (int k = 0; k < 4; k++) {
                    float a0 = ph[p * 8 + k * 2], a1 = ph[(1 - p) * 8 + k * 2 + 1];
                    g_d2m[p * 12 + k]     = make_float2(cosf(a0), cosf(a1));
                    g_d2m[p * 12 + 4 + k] = make_float2(sinf(a0), sinf(a1));
                    g_d2m[p * 12 + 8 + k] = make_float2(-sinf(a0), -sinf(a1));
                }
        }
    }
    if (t == 1) {
        // B-spline bases on [-1,1) collapse to cubics: bs_j(x) = poly/48
        const float BP[4][4] = {
            {1.f, -3.f, 3.f, -1.f},
            {23.f, -15.f, -3.f, 3.f},
            {23.f, 15.f, -3.f, -3.f},
            {1.f, 3.f, 3.f, 1.f}
        };
        const float inv48 = 1.0f / 48.0f;
        for (int o = 0; o < 7; o++) {
            float c0sum = 0.f;
            for (int in = 0; in < 4; in++) {
                float P[4] = {0.f, 0.f, 0.f, 0.f};
                for (int j = 0; j < 4; j++) {
                    float w = spline_w[o * 16 + in * 4 + j] * inv48;
                    for (int k = 0; k < 4; k++) P[k] += w * BP[j][k];
                }
                g_kan[o * 20 + in]      = base_w[o * 4 + in];
                g_kan[o * 20 + 4 + in]  = P[1];
                g_kan[o * 20 + 8 + in]  = P[2];
                g_kan[o * 20 + 12 + in] = P[3];
                c0sum += P[0];
            }
            g_kan[o * 20 + 16] = c0sum;
        }
    }
}

// ---------------- split-state gates (round-8 layout) ----------------
// thread bit p = q0; regs k: bit1=q1, bit0=q2; f32x2 lane = q3. State R[4], I[4].
// "Mixed" rep after a skipped HIXCH: own reg = (true_p.lo, true_{1-p}.hi).

struct RYC {
    ull D0, D1;             // q0 sweep consts (plain: lane-dup; fused: lane-mixed)
    ull cc1, ss1, ns1;      // q1
    ull cc2, ss2, ns2;      // q2
    ull cc3, sm3;           // q3 (lane-mixed (-s, s))
};

__device__ __forceinline__ void ry4(ull* R, ull* I, const RYC& c) {
    // q0 (thread axis): out = D0 (.) mine + D1 (.) shfl
    {
        ull PR0 = SHFL64(R[0]), PR1 = SHFL64(R[1]), PR2 = SHFL64(R[2]), PR3 = SHFL64(R[3]);
        ull PI0 = SHFL64(I[0]), PI1 = SHFL64(I[1]), PI2 = SHFL64(I[2]), PI3 = SHFL64(I[3]);
        R[0] = F2FMA(c.D1, PR0, F2MUL(c.D0, R[0]));
        R[1] = F2FMA(c.D1, PR1, F2MUL(c.D0, R[1]));
        R[2] = F2FMA(c.D1, PR2, F2MUL(c.D0, R[2]));
        R[3] = F2FMA(c.D1, PR3, F2MUL(c.D0, R[3]));
        I[0] = F2FMA(c.D1, PI0, F2MUL(c.D0, I[0]));
        I[1] = F2FMA(c.D1, PI1, F2MUL(c.D0, I[1]));
        I[2] = F2FMA(c.D1, PI2, F2MUL(c.D0, I[2]));
        I[3] = F2FMA(c.D1, PI3, F2MUL(c.D0, I[3]));
    }
    // q1: pairs (0,2),(1,3)
    {
        ull a, b;
        a = R[0]; b = R[2]; R[0] = F2FMA(c.ns1, b, F2MUL(c.cc1, a)); R[2] = F2FMA(c.ss1, a, F2MUL(c.cc1, b));
        a = R[1]; b = R[3]; R[1] = F2FMA(c.ns1, b, F2MUL(c.cc1, a)); R[3] = F2FMA(c.ss1, a, F2MUL(c.cc1, b));
        a = I[0]; b = I[2]; I[0] = F2FMA(c.ns1, b, F2MUL(c.cc1, a)); I[2] = F2FMA(c.ss1, a, F2MUL(c.cc1, b));
        a = I[1]; b = I[3]; I[1] = F2FMA(c.ns1, b, F2MUL(c.cc1, a)); I[3] = F2FMA(c.ss1, a, F2MUL(c.cc1, b));
    }
    // q2: pairs (0,1),(2,3)
    {
        ull a, b;
        a = R[0]; b = R[1]; R[0] = F2FMA(c.ns2, b, F2MUL(c.cc2, a)); R[1] = F2FMA(c.ss2, a, F2MUL(c.cc2, b));
        a = R[2]; b = R[3]; R[2] = F2FMA(c.ns2, b, F2MUL(c.cc2, a)); R[3] = F2FMA(c.ss2, a, F2MUL(c.cc2, b));
        a = I[0]; b = I[1]; I[0] = F2FMA(c.ns2, b, F2MUL(c.cc2, a)); I[1] = F2FMA(c.ss2, a, F2MUL(c.cc2, b));
        a = I[2]; b = I[3]; I[2] = F2FMA(c.ns2, b, F2MUL(c.cc2, a)); I[3] = F2FMA(c.ss2, a, F2MUL(c.cc2, b));
    }
    // q3 (lane axis)
#pragma unroll
    for (int k = 0; k < 4; k++) {
        ull v = R[k]; R[k] = F2FMA(c.sm3, SWAPH(v), F2MUL(c.cc3, v));
        ull w = I[k]; I[k] = F2FMA(c.sm3, SWAPH(w), F2MUL(c.cc3, w));
    }
}

__device__ __forceinline__ void diag_apply(ull* R, ull* I, const ull* d) {
#pragma unroll
    for (int k = 0; k < 4; k++) {
        ull C = d[k], S = d[4 + k], nS = d[8 + k];
        ull r = R[k], im = I[k];
        R[k] = F2FMA(nS, im, F2MUL(C, r));
        I[k] = F2FMA(S, r, F2MUL(C, im));
    }
}

// ring without final HIXCH (deferred into the following fused q0 sweep)
__device__ __forceinline__ void ring_normal_nox(ull* R, ull* I, int p) {
    {
        ull r0 = R[0], r1 = R[1], r2 = R[2], r3 = R[3];
        R[0] = p ? r2 : r0; R[2] = p ? r0 : r2;
        R[1] = p ? r3 : r1; R[3] = p ? r1 : r3;
        ull i0 = I[0], i1 = I[1], i2 = I[2], i3 = I[3];
        I[0] = p ? i2 : i0; I[2] = p ? i0 : i2;
        I[1] = p ? i3 : i1; I[3] = p ? i1 : i3;
    }
    { ull t = R[2]; R[2] = R[3]; R[3] = t; t = I[2]; I[2] = I[3]; I[3] = t; }
    R[1] = SWAPH(R[1]); R[3] = SWAPH(R[3]);
    I[1] = SWAPH(I[1]); I[3] = SWAPH(I[3]);
    // CNOT(q3,q0): SKIPPED -> mixed representation
}

// reversed ring: C(1,0) C(2,1) C(3,2) C(0,3)  [round-4 verified]
__device__ __forceinline__ void ring_rev(ull* R, ull* I, int p) {
    R[2] = SHFL64(R[2]); R[3] = SHFL64(R[3]);
    I[2] = SHFL64(I[2]); I[3] = SHFL64(I[3]);
    { ull t = R[1]; R[1] = R[3]; R[3] = t; t = I[1]; I[1] = I[3]; I[3] = t; }
    {
        ull a = R[0], b = R[1]; R[0] = MIXLH(a, b); R[1] = MIXLH(b, a);
        ull c = R[2], d = R[3]; R[2] = MIXLH(c, d); R[3] = MIXLH(d, c);
        ull e = I[0], f = I[1]; I[0] = MIXLH(e, f); I[1] = MIXLH(f, e);
        ull g = I[2], h = I[3]; I[2] = MIXLH(g, h); I[3] = MIXLH(h, g);
    }
#pragma unroll
    for (int k = 0; k < 4; k++) {
        R[k] = p ? SWAPH(R[k]) : R[k];
        I[k] = p ? SWAPH(I[k]) : I[k];
    }
}

// fused feature-map phases for this thread's half [round-4 verified]
__device__ __forceinline__ void phases8(const float* ang, int p, float* ph) {
    float b0 = 0.5f * ang[0], b1 = 0.5f * ang[1], b2 = 0.5f * ang[2], b3 = 0.5f * ang[3];
    float b4 = 0.5f * ang[4], b5 = 0.5f * ang[5], b6 = 0.5f * ang[6];
    float t01 = b0 + b1, d01 = b0 - b1;
    float uA = p ? (d01 + b4) : (-t01 - b4);
    float uB = p ? (t01 - b4) : (-d01 + b4);
    float t23 = b2 + b3, d23 = b2 - b3;
    float e00 = -t23 - b6, e01 = -d23 + b6, e10 = d23 + b6, e11 = t23 - b6;
    ph[0] = uA + (e00 - b5); ph[1] = uA + (e01 - b5);
    ph[2] = uA + (e10 + b5); ph[3] = uA + (e11 + b5);
    ph[4] = uB + (e00 + b5); ph[5] = uB + (e01 + b5);
    ph[6] = uB + (e10 - b5); ph[7] = uB + (e11 - b5);
}

__device__ __forceinline__ void qcell(const float* h_ang, const float* x_ang,
                                      const ull* d1, const ull* d2,
                                      const float* off1, const float* off2,
                                      const RYC& ry0, const RYC& ry1, const RYC& ry2,
                                      const RYC& ryl,
                                      int p, float sgnp, float* ev) {
    ull R[4], I[4];
    float ph[8];

    // D1 (data + const Dphi_1a offsets) on uniform state
    phases8(h_ang, p, ph);
#pragma unroll
    for (int s = 0; s < 8; s++) ph[s] += off1[s];
#pragma unroll
    for (int k = 0; k < 4; k++) {
        float s0, c0, s1, c1;
        __sincosf(ph[2 * k], &s0, &c0);
        __sincosf(ph[2 * k + 1], &s1, &c1);
        R[k] = PACK2(c0, c1); I[k] = PACK2(s0, s1);
    }

    // ansatz 1
    ry4(R, I, ry0);                // RY of layer 1a (plain)
    diag_apply(R, I, d1);          // Domega_1a * RZ(C_l2a)∘ring  (true rep)
    ring_normal_nox(R, I, p);      // -> mixed rep
    ry4(R, I, ryl);                // RY(B_l2a), fused q0 restores true rep
    ring_rev(R, I, p);

    // D2 (data + const offsets incl. RZ(A_l2a)∘ring_rev)
    phases8(x_ang, p, ph);
#pragma unroll
    for (int s = 0; s < 8; s++) ph[s] += off2[s];
#pragma unroll
    for (int k = 0; k < 4; k++) {
        float s0, c0, s1, c1;
        __sincosf(ph[2 * k], &s0, &c0);
        __sincosf(ph[2 * k + 1], &s1, &c1);
        ull c = PACK2(c0, c1), s = PACK2(s0, s1);
        ull nr = F2SUB(F2MUL(c, R[k]), F2MUL(s, I[k]));
        I[k] = F2FMA(s, R[k], F2MUL(c, I[k]));
        R[k] = nr;
    }

    // ansatz 2
    ry4(R, I, ry1);                // RY of layer 1b (plain, true rep)
    ring_normal_nox(R, I, p);      // -> mixed rep
    diag_apply(R, I, d2);          // PREMIXED Domega_1b∘ring * Dphi_2b (stays mixed)
    ry4(R, I, ry2);                // fused q0 sweep restores true rep

    // measurement (final ring folded into parities) [round-4 verified]
    float sv[4], dv[4];
#pragma unroll
    for (int k = 0; k < 4; k++) {
        ull P = F2FMA(I[k], I[k], F2MUL(R[k], R[k]));
        float2 f = UNPK(P);
        sv[k] = f.x + f.y;
        dv[k] = f.x - f.y;
    }
    float A = dv[0] - dv[1] - dv[2] + dv[3];
    float C = sv[0] + sv[1] - sv[2] - sv[3];
    float D = sv[0] - sv[1] - sv[2] + sv[3];
    float Ax = __shfl_xor_sync(0xFFFFFFFFu, A, 1);
    float Cx = __shfl_xor_sync(0xFFFFFFFFu, C, 1);
    float Dx = __shfl_xor_sync(0xFFFFFFFFu, D, 1);
    const float sc = 1.0f / 16.0f;
    ev[0] = (A + Ax) * sc;
    ev[1] = sgnp * (C - Cx) * sc;
    ev[2] = sgnp * (D - Dx) * sc;
    ev[3] = sgnp * (A - Ax) * sc;
}

__device__ __forceinline__ void kan_f(const float* hid, const float* W, float* oang) {
    float sl[4], x2[4], x3[4];
#pragma unroll
    for (int in = 0; in < 4; in++) {
        float x = hid[in];
        float e = __expf(-x);
        sl[in] = __fdividef(x, 1.0f + e);
        x2[in] = x * x;
        x3[in] = x2[in] * x;
    }
#pragma unroll
    for (int o = 0; o < 7; o++) {
        const float* w = W + o * 20;
        float acc = w[16];
#pragma unroll
        for (int in = 0; in < 4; in++) acc = fmaf(w[in], sl[in], acc);
#pragma unroll
        for (int in = 0; in < 4; in++) acc = fmaf(w[4 + in], hid[in], acc);
#pragma unroll
        for (int in = 0; in < 4; in++) acc = fmaf(w[8 + in], x2[in], acc);
#pragma unroll
        for (int in = 0; in < 4; in++) acc = fmaf(w[12 + in], x3[in], acc);
        oang[o] = acc;
    }
}

__global__ void __launch_bounds__(128, 2) qrnn_kernel(
    const float* __restrict__ inputs,      // [B, S, 4]
    const float* __restrict__ initial_t,   // [B, 7]
    const float* __restrict__ cw1,         // [16, 4]
    const float* __restrict__ cb1,         // [16]
    const float* __restrict__ cw2,         // [1, 16]
    const float* __restrict__ cb2,         // [1]
    float* __restrict__ out)               // [B]
{
    __shared__ float s_kan[140];
    int tid = threadIdx.x;
    for (int i = tid; i < 140; i += 128) s_kan[i] = g_kan[i];
    __syncthreads();

    int gtid = blockIdx.x * blockDim.x + tid;
    int e = gtid >> 1;           // element index
    int p = gtid & 1;            // q0 parity held by this thread
    float sgnp = p ? -1.0f : 1.0f;

    // per-thread constants (registers)
    float off1[8], off2[8];
#pragma unroll
    for (int s = 0; s < 8; s++) {
        off1[s] = g_off[p * 8 + s];
        off2[s] = g_off[16 + p * 8 + s];
    }
    RYC ry[4];   // 0:1a plain, 1:1b plain, 2:2b fused, 3:l2a fused
#pragma unroll
    for (int m = 0; m < 4; m++) {
        float c0 = g_ryf[m * 8 + 0], s0 = g_ryf[m * 8 + 1];
        float c1 = g_ryf[m * 8 + 2], s1 = g_ryf[m * 8 + 3];
        float c2 = g_ryf[m * 8 + 4], s2 = g_ryf[m * 8 + 5];
        float c3 = g_ryf[m * 8 + 6], s3 = g_ryf[m * 8 + 7];
        float s0p = p ? s0 : -s0;
        if (m >= 2) {
            // fused q0 sweep (consumes mixed rep): D0=(c,s_p), D1=(s_p,c)
            ry[m].D0 = PACK2(c0, s0p); ry[m].D1 = PACK2(s0p, c0);
        } else {
            ry[m].D0 = PACK2(c0, c0);  ry[m].D1 = PACK2(s0p, s0p);
        }
        ry[m].cc1 = PACK2(c1, c1); ry[m].ss1 = PACK2(s1, s1); ry[m].ns1 = PACK2(-s1, -s1);
        ry[m].cc2 = PACK2(c2, c2); ry[m].ss2 = PACK2(s2, s2); ry[m].ns2 = PACK2(-s2, -s2);
        ry[m].cc3 = PACK2(c3, c3); ry[m].sm3 = PACK2(-s3, s3);
    }
    // hoisted diagonals
    ull d1r[12], d2r[12];
    {
        const ull* b = reinterpret_cast<const ull*>(g_d1) + p * 12;
        const ull* c = reinterpret_cast<const ull*>(g_d2m) + p * 12;
#pragma unroll
        for (int i = 0; i < 12; i++) { d1r[i] = b[i]; d2r[i] = c[i]; }
    }

    float h_ang[7];
#pragma unroll
    for (int k = 0; k < 7; k++) h_ang[k] = initial_t[e * 7 + k];

    const float4* inp = reinterpret_cast<const float4*>(inputs) + (size_t)e * SLEN;

    float hid[4];
#pragma unroll 1
    for (int t = 0; t < SLEN; t++) {
        float4 xv = inp[t];
        float x_ang[7];
        x_ang[0] = xv.x; x_ang[1] = xv.y; x_ang[2] = xv.z; x_ang[3] = xv.w;
        x_ang[4] = (PI_F - xv.x) * (PI_F - xv.y);
        x_ang[5] = (PI_F - xv.y) * (PI_F - xv.z);
        x_ang[6] = (PI_F - xv.z) * (PI_F - xv.w);
        if (t > 0) kan_f(hid, s_kan, h_ang);
        qcell(h_ang, x_ang, d1r, d2r, off1, off2,
              ry[0], ry[1], ry[2], ry[3], p, sgnp, hid);
    }

    float o = cb2[0];
#pragma unroll 1
    for (int k = 0; k < 16; k++) {
        float a = cb1[k];
        a = fmaf(cw1[k * 4 + 0], hid[0], a);
        a = fmaf(cw1[k * 4 + 1], hid[1], a);
        a = fmaf(cw1[k * 4 + 2], hid[2], a);
        a = fmaf(cw1[k * 4 + 3], hid[3], a);
        o = fmaf(cw2[k], fmaxf(a, 0.0f), o);
    }
    if (p == 0) out[e] = o;
}

extern "C" void kernel_launch(void* const* d_in, const int* in_sizes, int n_in,
                              void* d_out, int out_size) {
    const float* inputs    = (const float*)d_in[0];
    const float* initial_t = (const float*)d_in[1];
    const float* p1        = (const float*)d_in[2];
    const float* p2        = (const float*)d_in[3];
    const float* base_w    = (const float*)d_in[4];
    const float* spline_w  = (const float*)d_in[5];
    const float* cw1       = (const float*)d_in[6];
    const float* cb1       = (const float*)d_in[7];
    const float* cw2       = (const float*)d_in[8];
    const float* cb2       = (const float*)d_in[9];

    setup_kernel<<<1, 32>>>(p1, p2, base_w, spline_w);
    qrnn_kernel<<<(BATCH * 2) / 128, 128>>>(inputs, initial_t,
                                            cw1, cb1, cw2, cb2, (float*)d_out);
}

// round 12
// speedup vs baseline: 1.1713x; 1.1063x over previous
#include <cuda_runtime.h>
#include <math.h>

#define SLEN 256
#define BATCH 16384
#define PI_F 3.14159265358979323846f
#define R2_F 0.70710678118654752440f

typedef unsigned long long ull;

// ---------- packed f32x2 primitives ----------
__device__ __forceinline__ ull F2MUL(ull a, ull b) {
    ull d; asm("mul.rn.f32x2 %0,%1,%2;" : "=l"(d) : "l"(a), "l"(b)); return d;
}
__device__ __forceinline__ ull F2FMA(ull a, ull b, ull c) {
    ull d; asm("fma.rn.f32x2 %0,%1,%2,%3;" : "=l"(d) : "l"(a), "l"(b), "l"(c)); return d;
}
__device__ __forceinline__ ull F2SUB(ull a, ull b) {
    ull d; asm("sub.rn.f32x2 %0,%1,%2;" : "=l"(d) : "l"(a), "l"(b)); return d;
}
__device__ __forceinline__ ull PACK2(float lo, float hi) {
    ull d; asm("mov.b64 %0,{%1,%2};" : "=l"(d) : "f"(lo), "f"(hi)); return d;
}
__device__ __forceinline__ float2 UNPK(ull v) {
    float2 r; asm("mov.b64 {%0,%1},%2;" : "=f"(r.x), "=f"(r.y) : "l"(v)); return r;
}
__device__ __forceinline__ ull SWAPH(ull v) {
    float2 r = UNPK(v); return PACK2(r.y, r.x);
}
__device__ __forceinline__ ull MIXLH(ull a, ull b) {   // (a.lo, b.hi)
    float2 x = UNPK(a), y = UNPK(b); return PACK2(x.x, y.y);
}
__device__ __forceinline__ ull SHFL64(ull v) {
    return __shfl_xor_sync(0xFFFFFFFFu, v, 1);
}

// ---------- precomputed constants ----------
// d1: plain diag (omega_1a * RZ(C_l2a)∘ring): [p][C0..3|S0..3|nS0..3]
__device__ float2 g_d1[24];
// d2m: PREMIXED diag (omega1b∘ring * phi2b): lo lane p, hi lane 1-p
__device__ float2 g_d2m[24];
// phase offsets: [diag 0/1][slot s=q0*8+q1*4+q2*2+q3]
__device__ float g_off[32];
// RY coefs: [layer m=0(1a),1(1b),2(2b),3(l2a ZYZ)][q][c,s]
__device__ float g_ryf[32];
// KAN folded weights: 7 outputs x 20
__device__ float g_kan[140];

__global__ void setup_kernel(const float* __restrict__ p1, const float* __restrict__ p2,
                             const float* __restrict__ base_w, const float* __restrict__ spline_w) {
    __shared__ float sA[4], sC[4];
    int t = threadIdx.x;

    // ---- threads 0-3: per-qubit ZYZ of l2a = H * Rot(a=0,l=1); RY coefs ----
    if (t < 4) {
        int q = t;
        {
            float phi = p1[12 + q * 3 + 0];
            float th  = p1[12 + q * 3 + 1];
            float om  = p1[12 + q * 3 + 2];
            float st, ct; sincosf(0.5f * th, &st, &ct);
            float sp, cp; sincosf(0.5f * (phi + om), &sp, &cp);
            float sm, cm; sincosf(0.5f * (phi - om), &sm, &cm);
            double ar =  (double)cp * ct, ai = -(double)sp * ct;
            double br = -(double)cm * st, bi = -(double)sm * st;
            double dr =  (double)cm * st, di = -(double)sm * st;
            double er =  (double)cp * ct, ei =  (double)sp * ct;
            const double r2 = 0.70710678118654752440;
            double u00r = (ar + dr) * r2, u00i = (ai + di) * r2;
            double u01r = (br + er) * r2, u01i = (bi + ei) * r2;
            double u10r = (ar - dr) * r2, u10i = (ai - di) * r2;
            double u11r = (br - er) * r2, u11i = (bi - ei) * r2;
            double detr = u00r * u11r - u00i * u11i - (u01r * u10r - u01i * u10i);
            double deti = u00r * u11i + u00i * u11r - (u01r * u10i + u01i * u10r);
            double alpha = 0.5 * atan2(deti, detr);
            double ca = cos(-alpha), sa = sin(-alpha);
            double v00r = u00r * ca - u00i * sa, v00i = u00r * sa + u00i * ca;
            double v10r = u10r * ca - u10i * sa, v10i = u10r * sa + u10i * ca;
            double cB = sqrt(v00r * v00r + v00i * v00i);
            double sB = sqrt(v10r * v10r + v10i * v10i);
            double a00 = (cB > 1e-12) ? atan2(v00i, v00r) : 0.0;
            double a10 = (sB > 1e-12) ? atan2(v10i, v10r) : 0.0;
            double ApC = -2.0 * a00;
            double AmC =  2.0 * a10;
            sA[q] = (float)(0.5 * (ApC + AmC));
            sC[q] = (float)(0.5 * (ApC - AmC));
            g_ryf[24 + q * 2 + 0] = (float)cB;
            g_ryf[24 + q * 2 + 1] = (float)sB;
        }
        // RY coefs for layers 1a(a0l0), 1b(a1l0), 2b(a1l1), this qubit
        for (int m = 0; m < 3; m++) {
            int a = (m == 0) ? 0 : 1;
            int l = (m == 2) ? 1 : 0;
            const float* pp = a ? p2 : p1;
            float th = pp[l * 12 + q * 3 + 1];
            g_ryf[m * 8 + q * 2 + 0] = cosf(0.5f * th);
            g_ryf[m * 8 + q * 2 + 1] = sinf(0.5f * th);
        }
    }
    __syncthreads();

    // ---- threads 0-15: one phase slot each for g_off, g_d1, g_d2m ----
    if (t < 16) {
        int s = t;
        int b0 = (s >> 3) & 1, b1 = (s >> 2) & 1, b2 = (s >> 1) & 1, b3 = s & 1;
        float h0 = b0 ? 0.5f : -0.5f, h1 = b1 ? 0.5f : -0.5f;
        float h2 = b2 ? 0.5f : -0.5f, h3 = b3 ? 0.5f : -0.5f;

        // g_off d=0: Dphi(1a)
        g_off[s] = h0 * p1[0] + h1 * p1[3] + h2 * p1[6] + h3 * p1[9];

        // g_off d=1: Dphi(1b) + phA at rinv(s)  [ring_rev inverse, closed form]
        {
            float v = h0 * p2[0] + h1 * p2[3] + h2 * p2[6] + h3 * p2[9];
            int r0 = b1 ^ b2 ^ b3;
            int r1 = b0 ^ b1 ^ b2 ^ b3;
            int r2 = b0 ^ b2 ^ b3;
            int r3 = b0 ^ b3;
            v += (r0 ? 0.5f : -0.5f) * sA[0] + (r1 ? 0.5f : -0.5f) * sA[1]
               + (r2 ? 0.5f : -0.5f) * sA[2] + (r3 ? 0.5f : -0.5f) * sA[3];
            g_off[16 + s] = v;
        }

        int p = b0, k = (s >> 1) & 3, lane = b3;

        // d1: Domega(1a) + phC at Mn(s)  [ring_normal forward map]
        {
            float ph = h0 * p1[2] + h1 * p1[5] + h2 * p1[8] + h3 * p1[11];
            int m1 = b1 ^ b0, m2 = b2 ^ m1, m3 = b3 ^ m2, m0 = b0 ^ m3;
            ph += (m0 ? 0.5f : -0.5f) * sC[0] + (m1 ? 0.5f : -0.5f) * sC[1]
                + (m2 ? 0.5f : -0.5f) * sC[2] + (m3 ? 0.5f : -0.5f) * sC[3];
            float cv, sv; sincosf(ph, &sv, &cv);
            float* f = reinterpret_cast<float*>(g_d1);
            int base = p * 24 + k * 2 + lane;
            f[base] = cv; f[base + 8] = sv; f[base + 16] = -sv;
        }

        // d2m: Dphi(2b)(s) + Domega(1b) at inv(s)  [ring_normal inverse, closed form],
        // premixed: lane0 -> dest p, lane1 -> dest 1-p
        {
            float ph = h0 * p2[12 + 0] + h1 * p2[12 + 3] + h2 * p2[12 + 6] + h3 * p2[12 + 9];
            int i0 = b0 ^ b3;
            int i1 = b0 ^ b1 ^ b3;
            int i2 = b1 ^ b2;
            int i3 = b2 ^ b3;
            ph += (i0 ? 0.5f : -0.5f) * p2[2] + (i1 ? 0.5f : -0.5f) * p2[5]
                + (i2 ? 0.5f : -0.5f) * p2[8] + (i3 ? 0.5f : -0.5f) * p2[11];
            float cv, sv; sincosf(ph, &sv, &cv);
            int pd = lane ? (1 - p) : p;
            float* f = reinterpret_cast<float*>(g_d2m);
            int base = pd * 24 + k * 2 + lane;
            f[base] = cv; f[base + 8] = sv; f[base + 16] = -sv;
        }
    }

    // ---- threads 16-22: one KAN row each ----
    if (t >= 16 && t < 23) {
        int o = t - 16;
        const float BP[4][4] = {
            {1.f, -3.f, 3.f, -1.f},
            {23.f, -15.f, -3.f, 3.f},
            {23.f, 15.f, -3.f, -3.f},
            {1.f, 3.f, 3.f, 1.f}
        };
        const float inv48 = 1.0f / 48.0f;
        float c0sum = 0.f;
        for (int in = 0; in < 4; in++) {
            float P[4] = {0.f, 0.f, 0.f, 0.f};
            for (int j = 0; j < 4; j++) {
                float w = spline_w[o * 16 + in * 4 + j] * inv48;
                for (int kk = 0; kk < 4; kk++) P[kk] += w * BP[j][kk];
            }
            g_kan[o * 20 + in]      = base_w[o * 4 + in];
            g_kan[o * 20 + 4 + in]  = P[1];
            g_kan[o * 20 + 8 + in]  = P[2];
            g_kan[o * 20 + 12 + in] = P[3];
            c0sum += P[0];
        }
        g_kan[o * 20 + 16] = c0sum;
    }
}

// ---------------- split-state gates (round-11 verified, unchanged) ----------------
// thread bit p = q0; regs k: bit1=q1, bit0=q2; f32x2 lane = q3. State R[4], I[4].

struct RYC {
    ull D0, D1;
    ull cc1, ss1, ns1;
    ull cc2, ss2, ns2;
    ull cc3, sm3;
};

__device__ __forceinline__ void ry4(ull* R, ull* I, const RYC& c) {
    {
        ull PR0 = SHFL64(R[0]), PR1 = SHFL64(R[1]), PR2 = SHFL64(R[2]), PR3 = SHFL64(R[3]);
        ull PI0 = SHFL64(I[0]), PI1 = SHFL64(I[1]), PI2 = SHFL64(I[2]), PI3 = SHFL64(I[3]);
        R[0] = F2FMA(c.D1, PR0, F2MUL(c.D0, R[0]));
        R[1] = F2FMA(c.D1, PR1, F2MUL(c.D0, R[1]));
        R[2] = F2FMA(c.D1, PR2, F2MUL(c.D0, R[2]));
        R[3] = F2FMA(c.D1, PR3, F2MUL(c.D0, R[3]));
        I[0] = F2FMA(c.D1, PI0, F2MUL(c.D0, I[0]));
        I[1] = F2FMA(c.D1, PI1, F2MUL(c.D0, I[1]));
        I[2] = F2FMA(c.D1, PI2, F2MUL(c.D0, I[2]));
        I[3] = F2FMA(c.D1, PI3, F2MUL(c.D0, I[3]));
    }
    {
        ull a, b;
        a = R[0]; b = R[2]; R[0] = F2FMA(c.ns1, b, F2MUL(c.cc1, a)); R[2] = F2FMA(c.ss1, a, F2MUL(c.cc1, b));
        a = R[1]; b = R[3]; R[1] = F2FMA(c.ns1, b, F2MUL(c.cc1, a)); R[3] = F2FMA(c.ss1, a, F2MUL(c.cc1, b));
        a = I[0]; b = I[2]; I[0] = F2FMA(c.ns1, b, F2MUL(c.cc1, a)); I[2] = F2FMA(c.ss1, a, F2MUL(c.cc1, b));
        a = I[1]; b = I[3]; I[1] = F2FMA(c.ns1, b, F2MUL(c.cc1, a)); I[3] = F2FMA(c.ss1, a, F2MUL(c.cc1, b));
    }
    {
        ull a, b;
        a = R[0]; b = R[1]; R[0] = F2FMA(c.ns2, b, F2MUL(c.cc2, a)); R[1] = F2FMA(c.ss2, a, F2MUL(c.cc2, b));
        a = R[2]; b = R[3]; R[2] = F2FMA(c.ns2, b, F2MUL(c.cc2, a)); R[3] = F2FMA(c.ss2, a, F2MUL(c.cc2, b));
        a = I[0]; b = I[1]; I[0] = F2FMA(c.ns2, b, F2MUL(c.cc2, a)); I[1] = F2FMA(c.ss2, a, F2MUL(c.cc2, b));
        a = I[2]; b = I[3]; I[2] = F2FMA(c.ns2, b, F2MUL(c.cc2, a)); I[3] = F2FMA(c.ss2, a, F2MUL(c.cc2, b));
    }
#pragma unroll
    for (int k = 0; k < 4; k++) {
        ull v = R[k]; R[k] = F2FMA(c.sm3, SWAPH(v), F2MUL(c.cc3, v));
        ull w = I[k]; I[k] = F2FMA(c.sm3, SWAPH(w), F2MUL(c.cc3, w));
    }
}

__device__ __forceinline__ void diag_apply(ull* R, ull* I, const ull* d) {
#pragma unroll
    for (int k = 0; k < 4; k++) {
        ull C = d[k], S = d[4 + k], nS = d[8 + k];
        ull r = R[k], im = I[k];
        R[k] = F2FMA(nS, im, F2MUL(C, r));
        I[k] = F2FMA(S, r, F2MUL(C, im));
    }
}

__device__ __forceinline__ void ring_normal_nox(ull* R, ull* I, int p) {
    {
        ull r0 = R[0], r1 = R[1], r2 = R[2], r3 = R[3];
        R[0] = p ? r2 : r0; R[2] = p ? r0 : r2;
        R[1] = p ? r3 : r1; R[3] = p ? r1 : r3;
        ull i0 = I[0], i1 = I[1], i2 = I[2], i3 = I[3];
        I[0] = p ? i2 : i0; I[2] = p ? i0 : i2;
        I[1] = p ? i3 : i1; I[3] = p ? i1 : i3;
    }
    { ull t = R[2]; R[2] = R[3]; R[3] = t; t = I[2]; I[2] = I[3]; I[3] = t; }
    R[1] = SWAPH(R[1]); R[3] = SWAPH(R[3]);
    I[1] = SWAPH(I[1]); I[3] = SWAPH(I[3]);
}

__device__ __forceinline__ void ring_rev(ull* R, ull* I, int p) {
    R[2] = SHFL64(R[2]); R[3] = SHFL64(R[3]);
    I[2] = SHFL64(I[2]); I[3] = SHFL64(I[3]);
    { ull t = R[1]; R[1] = R[3]; R[3] = t; t = I[1]; I[1] = I[3]; I[3] = t; }
    {
        ull a = R[0], b = R[1]; R[0] = MIXLH(a, b); R[1] = MIXLH(b, a);
        ull c = R[2], d = R[3]; R[2] = MIXLH(c, d); R[3] = MIXLH(d, c);
        ull e = I[0], f = I[1]; I[0] = MIXLH(e, f); I[1] = MIXLH(f, e);
        ull g = I[2], h = I[3]; I[2] = MIXLH(g, h); I[3] = MIXLH(h, g);
    }
#pragma unroll
    for (int k = 0; k < 4; k++) {
        R[k] = p ? SWAPH(R[k]) : R[k];
        I[k] = p ? SWAPH(I[k]) : I[k];
    }
}

__device__ __forceinline__ void phases8(const float* ang, int p, float* ph) {
    float b0 = 0.5f * ang[0], b1 = 0.5f * ang[1], b2 = 0.5f * ang[2], b3 = 0.5f * ang[3];
    float b4 = 0.5f * ang[4], b5 = 0.5f * ang[5], b6 = 0.5f * ang[6];
    float t01 = b0 + b1, d01 = b0 - b1;
    float uA = p ? (d01 + b4) : (-t01 - b4);
    float uB = p ? (t01 - b4) : (-d01 + b4);
    float t23 = b2 + b3, d23 = b2 - b3;
    float e00 = -t23 - b6, e01 = -d23 + b6, e10 = d23 + b6, e11 = t23 - b6;
    ph[0] = uA + (e00 - b5); ph[1] = uA + (e01 - b5);
    ph[2] = uA + (e10 + b5); ph[3] = uA + (e11 + b5);
    ph[4] = uB + (e00 + b5); ph[5] = uB + (e01 + b5);
    ph[6] = uB + (e10 - b5); ph[7] = uB + (e11 - b5);
}

__device__ __forceinline__ void qcell(const float* h_ang, const float* x_ang,
                                      const ull* d1, const ull* d2,
                                      const float* off1, const float* off2,
                                      const RYC& ry0, const RYC& ry1, const RYC& ry2,
                                      const RYC& ryl,
                                      int p, float sgnp, float* ev) {
    ull R[4], I[4];
    float ph[8];

    phases8(h_ang, p, ph);
#pragma unroll
    for (int s = 0; s < 8; s++) ph[s] += off1[s];
#pragma unroll
    for (int k = 0; k < 4; k++) {
        float s0, c0, s1, c1;
        __sincosf(ph[2 * k], &s0, &c0);
        __sincosf(ph[2 * k + 1], &s1, &c1);
        R[k] = PACK2(c0, c1); I[k] = PACK2(s0, s1);
    }

    // ansatz 1
    ry4(R, I, ry0);
    diag_apply(R, I, d1);
    ring_normal_nox(R, I, p);
    ry4(R, I, ryl);                // RY(B_l2a), fused q0 restores true rep
    ring_rev(R, I, p);

    // D2
    phases8(x_ang, p, ph);
#pragma unroll
    for (int s = 0; s < 8; s++) ph[s] += off2[s];
#pragma unroll
    for (int k = 0; k < 4; k++) {
        float s0, c0, s1, c1;
        __sincosf(ph[2 * k], &s0, &c0);
        __sincosf(ph[2 * k + 1], &s1, &c1);
        ull c = PACK2(c0, c1), s = PACK2(s0, s1);
        ull nr = F2SUB(F2MUL(c, R[k]), F2MUL(s, I[k]));
        I[k] = F2FMA(s, R[k], F2MUL(c, I[k]));
        R[k] = nr;
    }

    // ansatz 2
    ry4(R, I, ry1);
    ring_normal_nox(R, I, p);
    diag_apply(R, I, d2);
    ry4(R, I, ry2);

    // measurement
    float sv[4], dv[4];
#pragma unroll
    for (int k = 0; k < 4; k++) {
        ull P = F2FMA(I[k], I[k], F2MUL(R[k], R[k]));
        float2 f = UNPK(P);
        sv[k] = f.x + f.y;
        dv[k] = f.x - f.y;
    }
    float A = dv[0] - dv[1] - dv[2] + dv[3];
    float C = sv[0] + sv[1] - sv[2] - sv[3];
    float D = sv[0] - sv[1] - sv[2] + sv[3];
    float Ax = __shfl_xor_sync(0xFFFFFFFFu, A, 1);
    float Cx = __shfl_xor_sync(0xFFFFFFFFu, C, 1);
    float Dx = __shfl_xor_sync(0xFFFFFFFFu, D, 1);
    const float sc = 1.0f / 16.0f;
    ev[0] = (A + Ax) * sc;
    ev[1] = sgnp * (C - Cx) * sc;
    ev[2] = sgnp * (D - Dx) * sc;
    ev[3] = sgnp * (A - Ax) * sc;
}

__device__ __forceinline__ void kan_f(const float* hid, const float* W, float* oang) {
    float sl[4], x2[4], x3[4];
#pragma unroll
    for (int in = 0; in < 4; in++) {
        float x = hid[in];
        float e = __expf(-x);
        sl[in] = __fdividef(x, 1.0f + e);
        x2[in] = x * x;
        x3[in] = x2[in] * x;
    }
#pragma unroll
    for (int o = 0; o < 7; o++) {
        const float* w = W + o * 20;
        float acc = w[16];
#pragma unroll
        for (int in = 0; in < 4; in++) acc = fmaf(w[in], sl[in], acc);
#pragma unroll
        for (int in = 0; in < 4; in++) acc = fmaf(w[4 + in], hid[in], acc);
#pragma unroll
        for (int in = 0; in < 4; in++) acc = fmaf(w[8 + in], x2[in], acc);
#pragma unroll
        for (int in = 0; in < 4; in++) acc = fmaf(w[12 + in], x3[in], acc);
        oang[o] = acc;
    }
}

__global__ void __launch_bounds__(128, 2) qrnn_kernel(
    const float* __restrict__ inputs,      // [B, S, 4]
    const float* __restrict__ initial_t,   // [B, 7]
    const float* __restrict__ cw1,         // [16, 4]
    const float* __restrict__ cb1,         // [16]
    const float* __restrict__ cw2,         // [1, 16]
    const float* __restrict__ cb2,         // [1]
    float* __restrict__ out)               // [B]
{
    __shared__ float s_kan[140];
    int tid = threadIdx.x;
    for (int i = tid; i < 140; i += 128) s_kan[i] = g_kan[i];
    __syncthreads();

    int gtid = blockIdx.x * blockDim.x + tid;
    int e = gtid >> 1;
    int p = gtid & 1;
    float sgnp = p ? -1.0f : 1.0f;

    float off1[8], off2[8];
#pragma unroll
    for (int s = 0; s < 8; s++) {
        off1[s] = g_off[p * 8 + s];
        off2[s] = g_off[16 + p * 8 + s];
    }
    RYC ry[4];   // 0:1a plain, 1:1b plain, 2:2b fused, 3:l2a fused
#pragma unroll
    for (int m = 0; m < 4; m++) {
        float c0 = g_ryf[m * 8 + 0], s0 = g_ryf[m * 8 + 1];
        float c1 = g_ryf[m * 8 + 2], s1 = g_ryf[m * 8 + 3];
        float c2 = g_ryf[m * 8 + 4], s2 = g_ryf[m * 8 + 5];
        float c3 = g_ryf[m * 8 + 6], s3 = g_ryf[m * 8 + 7];
        float s0p = p ? s0 : -s0;
        if (m >= 2) {
            ry[m].D0 = PACK2(c0, s0p); ry[m].D1 = PACK2(s0p, c0);
        } else {
            ry[m].D0 = PACK2(c0, c0);  ry[m].D1 = PACK2(s0p, s0p);
        }
        ry[m].cc1 = PACK2(c1, c1); ry[m].ss1 = PACK2(s1, s1); ry[m].ns1 = PACK2(-s1, -s1);
        ry[m].cc2 = PACK2(c2, c2); ry[m].ss2 = PACK2(s2, s2); ry[m].ns2 = PACK2(-s2, -s2);
        ry[m].cc3 = PACK2(c3, c3); ry[m].sm3 = PACK2(-s3, s3);
    }
    ull d1r[12], d2r[12];
    {
        const ull* b = reinterpret_cast<const ull*>(g_d1) + p * 12;
        const ull* c = reinterpret_cast<const ull*>(g_d2m) + p * 12;
#pragma unroll
        for (int i = 0; i < 12; i++) { d1r[i] = b[i]; d2r[i] = c[i]; }
    }

    float h_ang[7];
#pragma unroll
    for (int k = 0; k < 7; k++) h_ang[k] = initial_t[e * 7 + k];

    const float4* inp = reinterpret_cast<const float4*>(inputs) + (size_t)e * SLEN;

    float hid[4];
#pragma unroll 1
    for (int t = 0; t < SLEN; t++) {
        float4 xv = inp[t];
        float x_ang[7];
        x_ang[0] = xv.x; x_ang[1] = xv.y; x_ang[2] = xv.z; x_ang[3] = xv.w;
        x_ang[4] = (PI_F - xv.x) * (PI_F - xv.y);
        x_ang[5] = (PI_F - xv.y) * (PI_F - xv.z);
        x_ang[6] = (PI_F - xv.z) * (PI_F - xv.w);
        if (t > 0) kan_f(hid, s_kan, h_ang);
        qcell(h_ang, x_ang, d1r, d2r, off1, off2,
              ry[0], ry[1], ry[2], ry[3], p, sgnp, hid);
    }

    float o = cb2[0];
#pragma unroll 1
    for (int k = 0; k < 16; k++) {
        float a = cb1[k];
        a = fmaf(cw1[k * 4 + 0], hid[0], a);
        a = fmaf(cw1[k * 4 + 1], hid[1], a);
        a = fmaf(cw1[k * 4 + 2], hid[2], a);
        a = fmaf(cw1[k * 4 + 3], hid[3], a);
        o = fmaf(cw2[k], fmaxf(a, 0.0f), o);
    }
    if (p == 0) out[e] = o;
}

extern "C" void kernel_launch(void* const* d_in, const int* in_sizes, int n_in,
                              void* d_out, int out_size) {
    const float* inputs    = (const float*)d_in[0];
    const float* initial_t = (const float*)d_in[1];
    const float* p1        = (const float*)d_in[2];
    const float* p2        = (const float*)d_in[3];
    const float* base_w    = (const float*)d_in[4];
    const float* spline_w  = (const float*)d_in[5];
    const float* cw1       = (const float*)d_in[6];
    const float* cb1       = (const float*)d_in[7];
    const float* cw2       = (const float*)d_in[8];
    const float* cb2       = (const float*)d_in[9];

    setup_kernel<<<1, 32>>>(p1, p2, base_w, spline_w);
    qrnn_kernel<<<(BATCH * 2) / 128, 128>>>(inputs, initial_t,
                                            cw1, cb1, cw2, cb2, (float*)d_out);
}

// round 13
// speedup vs baseline: 1.1960x; 1.0211x over previous
#include <cuda_runtime.h>
#include <math.h>

#define SLEN 256
#define BATCH 16384
#define PI_F 3.14159265358979323846f
#define R2_F 0.70710678118654752440f

typedef unsigned long long ull;

// ---------- packed f32x2 primitives ----------
__device__ __forceinline__ ull F2MUL(ull a, ull b) {
    ull d; asm("mul.rn.f32x2 %0,%1,%2;" : "=l"(d) : "l"(a), "l"(b)); return d;
}
__device__ __forceinline__ ull F2FMA(ull a, ull b, ull c) {
    ull d; asm("fma.rn.f32x2 %0,%1,%2,%3;" : "=l"(d) : "l"(a), "l"(b), "l"(c)); return d;
}
__device__ __forceinline__ ull F2SUB(ull a, ull b) {
    ull d; asm("sub.rn.f32x2 %0,%1,%2;" : "=l"(d) : "l"(a), "l"(b)); return d;
}
__device__ __forceinline__ ull PACK2(float lo, float hi) {
    ull d; asm("mov.b64 %0,{%1,%2};" : "=l"(d) : "f"(lo), "f"(hi)); return d;
}
__device__ __forceinline__ float2 UNPK(ull v) {
    float2 r; asm("mov.b64 {%0,%1},%2;" : "=f"(r.x), "=f"(r.y) : "l"(v)); return r;
}
__device__ __forceinline__ ull SWAPH(ull v) {
    float2 r = UNPK(v); return PACK2(r.y, r.x);
}
__device__ __forceinline__ ull MIXLH(ull a, ull b) {   // (a.lo, b.hi)
    float2 x = UNPK(a), y = UNPK(b); return PACK2(x.x, y.y);
}
__device__ __forceinline__ ull SHFL64(ull v) {
    return __shfl_xor_sync(0xFFFFFFFFu, v, 1);
}

// ---------- precomputed constants ----------
__device__ float2 g_d1[24];     // diag (omega_1a * RZ(C_l2a)∘ring): [p][C|S|nS]
__device__ float2 g_d2m[24];    // PREMIXED diag (omega1b∘ring * phi2b)
__device__ float g_off[32];     // phase offsets [diag 0/1][slot]
__device__ float g_ryf[32];     // RY coefs [layer 0..3][q][c,s]
__device__ float g_kan[140];    // scratch rows (x0.5 folded)
__device__ float2 g_kanp[51];   // packed KAN: pairs (0,1),(2,3),(4,5) x 17
__device__ float g_kans[17];    // KAN row 6

__global__ void setup_kernel(const float* __restrict__ p1, const float* __restrict__ p2,
                             const float* __restrict__ base_w, const float* __restrict__ spline_w) {
    __shared__ float sA[4], sC[4];
    int t = threadIdx.x;

    // ---- threads 0-3: per-qubit ZYZ of l2a = H * Rot(a=0,l=1); RY coefs ----
    if (t < 4) {
        int q = t;
        {
            float phi = p1[12 + q * 3 + 0];
            float th  = p1[12 + q * 3 + 1];
            float om  = p1[12 + q * 3 + 2];
            float st, ct; sincosf(0.5f * th, &st, &ct);
            float sp, cp; sincosf(0.5f * (phi + om), &sp, &cp);
            float sm, cm; sincosf(0.5f * (phi - om), &sm, &cm);
            double ar =  (double)cp * ct, ai = -(double)sp * ct;
            double br = -(double)cm * st, bi = -(double)sm * st;
            double dr =  (double)cm * st, di = -(double)sm * st;
            double er =  (double)cp * ct, ei =  (double)sp * ct;
            const double r2 = 0.70710678118654752440;
            double u00r = (ar + dr) * r2, u00i = (ai + di) * r2;
            double u01r = (br + er) * r2, u01i = (bi + ei) * r2;
            double u10r = (ar - dr) * r2, u10i = (ai - di) * r2;
            double u11r = (br - er) * r2, u11i = (bi - ei) * r2;
            double detr = u00r * u11r - u00i * u11i - (u01r * u10r - u01i * u10i);
            double deti = u00r * u11i + u00i * u11r - (u01r * u10i + u01i * u10r);
            double alpha = 0.5 * atan2(deti, detr);
            double ca = cos(-alpha), sa = sin(-alpha);
            double v00r = u00r * ca - u00i * sa, v00i = u00r * sa + u00i * ca;
            double v10r = u10r * ca - u10i * sa, v10i = u10r * sa + u10i * ca;
            double cB = sqrt(v00r * v00r + v00i * v00i);
            double sB = sqrt(v10r * v10r + v10i * v10i);
            double a00 = (cB > 1e-12) ? atan2(v00i, v00r) : 0.0;
            double a10 = (sB > 1e-12) ? atan2(v10i, v10r) : 0.0;
            double ApC = -2.0 * a00;
            double AmC =  2.0 * a10;
            sA[q] = (float)(0.5 * (ApC + AmC));
            sC[q] = (float)(0.5 * (ApC - AmC));
            g_ryf[24 + q * 2 + 0] = (float)cB;
            g_ryf[24 + q * 2 + 1] = (float)sB;
        }
        for (int m = 0; m < 3; m++) {
            int a = (m == 0) ? 0 : 1;
            int l = (m == 2) ? 1 : 0;
            const float* pp = a ? p2 : p1;
            float th = pp[l * 12 + q * 3 + 1];
            g_ryf[m * 8 + q * 2 + 0] = cosf(0.5f * th);
            g_ryf[m * 8 + q * 2 + 1] = sinf(0.5f * th);
        }
    }
    __syncthreads();

    // ---- threads 0-15: one phase slot each for g_off, g_d1, g_d2m ----
    if (t < 16) {
        int s = t;
        int b0 = (s >> 3) & 1, b1 = (s >> 2) & 1, b2 = (s >> 1) & 1, b3 = s & 1;
        float h0 = b0 ? 0.5f : -0.5f, h1 = b1 ? 0.5f : -0.5f;
        float h2 = b2 ? 0.5f : -0.5f, h3 = b3 ? 0.5f : -0.5f;

        g_off[s] = h0 * p1[0] + h1 * p1[3] + h2 * p1[6] + h3 * p1[9];

        {
            float v = h0 * p2[0] + h1 * p2[3] + h2 * p2[6] + h3 * p2[9];
            int r0 = b1 ^ b2 ^ b3;
            int r1 = b0 ^ b1 ^ b2 ^ b3;
            int r2 = b0 ^ b2 ^ b3;
            int r3 = b0 ^ b3;
            v += (r0 ? 0.5f : -0.5f) * sA[0] + (r1 ? 0.5f : -0.5f) * sA[1]
               + (r2 ? 0.5f : -0.5f) * sA[2] + (r3 ? 0.5f : -0.5f) * sA[3];
            g_off[16 + s] = v;
        }

        int p = b0, k = (s >> 1) & 3, lane = b3;

        {
            float ph = h0 * p1[2] + h1 * p1[5] + h2 * p1[8] + h3 * p1[11];
            int m1 = b1 ^ b0, m2 = b2 ^ m1, m3 = b3 ^ m2, m0 = b0 ^ m3;
            ph += (m0 ? 0.5f : -0.5f) * sC[0] + (m1 ? 0.5f : -0.5f) * sC[1]
                + (m2 ? 0.5f : -0.5f) * sC[2] + (m3 ? 0.5f : -0.5f) * sC[3];
            float cv, sv; sincosf(ph, &sv, &cv);
            float* f = reinterpret_cast<float*>(g_d1);
            int base = p * 24 + k * 2 + lane;
            f[base] = cv; f[base + 8] = sv; f[base + 16] = -sv;
        }

        {
            float ph = h0 * p2[12 + 0] + h1 * p2[12 + 3] + h2 * p2[12 + 6] + h3 * p2[12 + 9];
            int i0 = b0 ^ b3;
            int i1 = b0 ^ b1 ^ b3;
            int i2 = b1 ^ b2;
            int i3 = b2 ^ b3;
            ph += (i0 ? 0.5f : -0.5f) * p2[2] + (i1 ? 0.5f : -0.5f) * p2[5]
                + (i2 ? 0.5f : -0.5f) * p2[8] + (i3 ? 0.5f : -0.5f) * p2[11];
            float cv, sv; sincosf(ph, &sv, &cv);
            int pd = lane ? (1 - p) : p;
            float* f = reinterpret_cast<float*>(g_d2m);
            int base = pd * 24 + k * 2 + lane;
            f[base] = cv; f[base + 8] = sv; f[base + 16] = -sv;
        }
    }

    // ---- threads 16-22: one KAN row each (x0.5 folded into ALL coefs) ----
    if (t >= 16 && t < 23) {
        int o = t - 16;
        const float BP[4][4] = {
            {1.f, -3.f, 3.f, -1.f},
            {23.f, -15.f, -3.f, 3.f},
            {23.f, 15.f, -3.f, -3.f},
            {1.f, 3.f, 3.f, 1.f}
        };
        const float inv48 = 0.5f / 48.0f;   // 0.5 phase-fold
        float c0sum = 0.f;
        for (int in = 0; in < 4; in++) {
            float P[4] = {0.f, 0.f, 0.f, 0.f};
            for (int j = 0; j < 4; j++) {
                float w = spline_w[o * 16 + in * 4 + j] * inv48;
                for (int kk = 0; kk < 4; kk++) P[kk] += w * BP[j][kk];
            }
            g_kan[o * 20 + in]      = 0.5f * base_w[o * 4 + in];
            g_kan[o * 20 + 4 + in]  = P[1];
            g_kan[o * 20 + 8 + in]  = P[2];
            g_kan[o * 20 + 12 + in] = P[3];
            c0sum += P[0];
        }
        g_kan[o * 20 + 16] = c0sum;
    }
    __syncthreads();

    // ---- threads 0-3: pack KAN rows into f2 pairs / scalar row ----
    if (t < 3) {
        for (int k = 0; k < 17; k++)
            g_kanp[t * 17 + k] = make_float2(g_kan[(2 * t) * 20 + k],
                                             g_kan[(2 * t + 1) * 20 + k]);
    }
    if (t == 3) {
        for (int k = 0; k < 17; k++) g_kans[k] = g_kan[6 * 20 + k];
    }
}

// ---------------- split-state gates (round-12 verified, unchanged) ----------------
// thread bit p = q0; regs k: bit1=q1, bit0=q2; f32x2 lane = q3. State R[4], I[4].

struct RYC {
    ull D0, D1;
    ull cc1, ss1, ns1;
    ull cc2, ss2, ns2;
    ull cc3, sm3;
};

__device__ __forceinline__ void ry4(ull* R, ull* I, const RYC& c) {
    {
        ull PR0 = SHFL64(R[0]), PR1 = SHFL64(R[1]), PR2 = SHFL64(R[2]), PR3 = SHFL64(R[3]);
        ull PI0 = SHFL64(I[0]), PI1 = SHFL64(I[1]), PI2 = SHFL64(I[2]), PI3 = SHFL64(I[3]);
        R[0] = F2FMA(c.D1, PR0, F2MUL(c.D0, R[0]));
        R[1] = F2FMA(c.D1, PR1, F2MUL(c.D0, R[1]));
        R[2] = F2FMA(c.D1, PR2, F2MUL(c.D0, R[2]));
        R[3] = F2FMA(c.D1, PR3, F2MUL(c.D0, R[3]));
        I[0] = F2FMA(c.D1, PI0, F2MUL(c.D0, I[0]));
        I[1] = F2FMA(c.D1, PI1, F2MUL(c.D0, I[1]));
        I[2] = F2FMA(c.D1, PI2, F2MUL(c.D0, I[2]));
        I[3] = F2FMA(c.D1, PI3, F2MUL(c.D0, I[3]));
    }
    {
        ull a, b;
        a = R[0]; b = R[2]; R[0] = F2FMA(c.ns1, b, F2MUL(c.cc1, a)); R[2] = F2FMA(c.ss1, a, F2MUL(c.cc1, b));
        a = R[1]; b = R[3]; R[1] = F2FMA(c.ns1, b, F2MUL(c.cc1, a)); R[3] = F2FMA(c.ss1, a, F2MUL(c.cc1, b));
        a = I[0]; b = I[2]; I[0] = F2FMA(c.ns1, b, F2MUL(c.cc1, a)); I[2] = F2FMA(c.ss1, a, F2MUL(c.cc1, b));
        a = I[1]; b = I[3]; I[1] = F2FMA(c.ns1, b, F2MUL(c.cc1, a)); I[3] = F2FMA(c.ss1, a, F2MUL(c.cc1, b));
    }
    {
        ull a, b;
        a = R[0]; b = R[1]; R[0] = F2FMA(c.ns2, b, F2MUL(c.cc2, a)); R[1] = F2FMA(c.ss2, a, F2MUL(c.cc2, b));
        a = R[2]; b = R[3]; R[2] = F2FMA(c.ns2, b, F2MUL(c.cc2, a)); R[3] = F2FMA(c.ss2, a, F2MUL(c.cc2, b));
        a = I[0]; b = I[1]; I[0] = F2FMA(c.ns2, b, F2MUL(c.cc2, a)); I[1] = F2FMA(c.ss2, a, F2MUL(c.cc2, b));
        a = I[2]; b = I[3]; I[2] = F2FMA(c.ns2, b, F2MUL(c.cc2, a)); I[3] = F2FMA(c.ss2, a, F2MUL(c.cc2, b));
    }
#pragma unroll
    for (int k = 0; k < 4; k++) {
        ull v = R[k]; R[k] = F2FMA(c.sm3, SWAPH(v), F2MUL(c.cc3, v));
        ull w = I[k]; I[k] = F2FMA(c.sm3, SWAPH(w), F2MUL(c.cc3, w));
    }
}

__device__ __forceinline__ void diag_apply(ull* R, ull* I, const ull* d) {
#pragma unroll
    for (int k = 0; k < 4; k++) {
        ull C = d[k], S = d[4 + k], nS = d[8 + k];
        ull r = R[k], im = I[k];
        R[k] = F2FMA(nS, im, F2MUL(C, r));
        I[k] = F2FMA(S, r, F2MUL(C, im));
    }
}

__device__ __forceinline__ void ring_normal_nox(ull* R, ull* I, int p) {
    {
        ull r0 = R[0], r1 = R[1], r2 = R[2], r3 = R[3];
        R[0] = p ? r2 : r0; R[2] = p ? r0 : r2;
        R[1] = p ? r3 : r1; R[3] = p ? r1 : r3;
        ull i0 = I[0], i1 = I[1], i2 = I[2], i3 = I[3];
        I[0] = p ? i2 : i0; I[2] = p ? i0 : i2;
        I[1] = p ? i3 : i1; I[3] = p ? i1 : i3;
    }
    { ull t = R[2]; R[2] = R[3]; R[3] = t; t = I[2]; I[2] = I[3]; I[3] = t; }
    R[1] = SWAPH(R[1]); R[3] = SWAPH(R[3]);
    I[1] = SWAPH(I[1]); I[3] = SWAPH(I[3]);
}

__device__ __forceinline__ void ring_rev(ull* R, ull* I, int p) {
    R[2] = SHFL64(R[2]); R[3] = SHFL64(R[3]);
    I[2] = SHFL64(I[2]); I[3] = SHFL64(I[3]);
    { ull t = R[1]; R[1] = R[3]; R[3] = t; t = I[1]; I[1] = I[3]; I[3] = t; }
    {
        ull a = R[0], b = R[1]; R[0] = MIXLH(a, b); R[1] = MIXLH(b, a);
        ull c = R[2], d = R[3]; R[2] = MIXLH(c, d); R[3] = MIXLH(d, c);
        ull e = I[0], f = I[1]; I[0] = MIXLH(e, f); I[1] = MIXLH(f, e);
        ull g = I[2], h = I[3]; I[2] = MIXLH(g, h); I[3] = MIXLH(h, g);
    }
#pragma unroll
    for (int k = 0; k < 4; k++) {
        R[k] = p ? SWAPH(R[k]) : R[k];
        I[k] = p ? SWAPH(I[k]) : I[k];
    }
}

// fused feature-map phases; ang is PRE-HALVED
__device__ __forceinline__ void phases8h(const float* ang, int p, float* ph) {
    float b0 = ang[0], b1 = ang[1], b2 = ang[2], b3 = ang[3];
    float b4 = ang[4], b5 = ang[5], b6 = ang[6];
    float t01 = b0 + b1, d01 = b0 - b1;
    float uA = p ? (d01 + b4) : (-t01 - b4);
    float uB = p ? (t01 - b4) : (-d01 + b4);
    float t23 = b2 + b3, d23 = b2 - b3;
    float e00 = -t23 - b6, e01 = -d23 + b6, e10 = d23 + b6, e11 = t23 - b6;
    ph[0] = uA + (e00 - b5); ph[1] = uA + (e01 - b5);
    ph[2] = uA + (e10 + b5); ph[3] = uA + (e11 + b5);
    ph[4] = uB + (e00 + b5); ph[5] = uB + (e01 + b5);
    ph[6] = uB + (e10 - b5); ph[7] = uB + (e11 - b5);
}

__device__ __forceinline__ void qcell(const float* h_ang, const float* x_ang,
                                      const ull* d1, const ull* d2,
                                      const float* off1, const float* off2,
                                      const RYC& ry0, const RYC& ry1, const RYC& ry2,
                                      const RYC& ryl,
                                      int p, float sgnp, float* ev) {
    ull R[4], I[4];
    float ph[8];

    phases8h(h_ang, p, ph);
#pragma unroll
    for (int s = 0; s < 8; s++) ph[s] += off1[s];
#pragma unroll
    for (int k = 0; k < 4; k++) {
        float s0, c0, s1, c1;
        __sincosf(ph[2 * k], &s0, &c0);
        __sincosf(ph[2 * k + 1], &s1, &c1);
        R[k] = PACK2(c0, c1); I[k] = PACK2(s0, s1);
    }

    // ansatz 1
    ry4(R, I, ry0);
    diag_apply(R, I, d1);
    ring_normal_nox(R, I, p);
    ry4(R, I, ryl);
    ring_rev(R, I, p);

    // D2
    phases8h(x_ang, p, ph);
#pragma unroll
    for (int s = 0; s < 8; s++) ph[s] += off2[s];
#pragma unroll
    for (int k = 0; k < 4; k++) {
        float s0, c0, s1, c1;
        __sincosf(ph[2 * k], &s0, &c0);
        __sincosf(ph[2 * k + 1], &s1, &c1);
        ull c = PACK2(c0, c1), s = PACK2(s0, s1);
        ull nr = F2SUB(F2MUL(c, R[k]), F2MUL(s, I[k]));
        I[k] = F2FMA(s, R[k], F2MUL(c, I[k]));
        R[k] = nr;
    }

    // ansatz 2
    ry4(R, I, ry1);
    ring_normal_nox(R, I, p);
    diag_apply(R, I, d2);
    ry4(R, I, ry2);

    // measurement
    float sv[4], dv[4];
#pragma unroll
    for (int k = 0; k < 4; k++) {
        ull P = F2FMA(I[k], I[k], F2MUL(R[k], R[k]));
        float2 f = UNPK(P);
        sv[k] = f.x + f.y;
        dv[k] = f.x - f.y;
    }
    float A = dv[0] - dv[1] - dv[2] + dv[3];
    float C = sv[0] + sv[1] - sv[2] - sv[3];
    float D = sv[0] - sv[1] - sv[2] + sv[3];
    float Ax = __shfl_xor_sync(0xFFFFFFFFu, A, 1);
    float Cx = __shfl_xor_sync(0xFFFFFFFFu, C, 1);
    float Dx = __shfl_xor_sync(0xFFFFFFFFu, D, 1);
    const float sc = 1.0f / 16.0f;
    ev[0] = (A + Ax) * sc;
    ev[1] = sgnp * (C - Cx) * sc;
    ev[2] = sgnp * (D - Dx) * sc;
    ev[3] = sgnp * (A - Ax) * sc;
}

// Packed KAN: outputs (0,1),(2,3),(4,5) in f2 accumulators + scalar o6.
// Weights pre-halved; outputs are PRE-HALVED angles.
__device__ __forceinline__ void kan_fp(const float* hid, const ull* Wp,
                                       const float* Ws, float* oang) {
    float f[16];
#pragma unroll
    for (int in = 0; in < 4; in++) {
        float x = hid[in];
        float e = __expf(-x);
        f[in] = __fdividef(x, 1.0f + e);     // silu
        f[4 + in] = x;
        float x2 = x * x;
        f[8 + in] = x2;
        f[12 + in] = x2 * x;
    }
    ull a0 = Wp[16], a1 = Wp[17 + 16], a2 = Wp[34 + 16];
    float acc3 = Ws[16];
#pragma unroll
    for (int i = 0; i < 16; i++) {
        ull F = PACK2(f[i], f[i]);
        a0 = F2FMA(Wp[i], F, a0);
        a1 = F2FMA(Wp[17 + i], F, a1);
        a2 = F2FMA(Wp[34 + i], F, a2);
        acc3 = fmaf(Ws[i], f[i], acc3);
    }
    float2 r0 = UNPK(a0), r1 = UNPK(a1), r2 = UNPK(a2);
    oang[0] = r0.x; oang[1] = r0.y;
    oang[2] = r1.x; oang[3] = r1.y;
    oang[4] = r2.x; oang[5] = r2.y;
    oang[6] = acc3;
}

__global__ void __launch_bounds__(128, 2) qrnn_kernel(
    const float* __restrict__ inputs,      // [B, S, 4]
    const float* __restrict__ initial_t,   // [B, 7]
    const float* __restrict__ cw1,         // [16, 4]
    const float* __restrict__ cb1,         // [16]
    const float* __restrict__ cw2,         // [1, 16]
    const float* __restrict__ cb2,         // [1]
    float* __restrict__ out)               // [B]
{
    __shared__ __align__(16) ull s_kanp[51];
    __shared__ float s_kans[17];
    int tid = threadIdx.x;
    {
        const ull* a = reinterpret_cast<const ull*>(g_kanp);
        if (tid < 51) s_kanp[tid] = a[tid];
        if (tid >= 64 && tid < 81) s_kans[tid - 64] = g_kans[tid - 64];
    }
    __syncthreads();

    int gtid = blockIdx.x * blockDim.x + tid;
    int e = gtid >> 1;
    int p = gtid & 1;
    float sgnp = p ? -1.0f : 1.0f;

    float off1[8], off2[8];
#pragma unroll
    for (int s = 0; s < 8; s++) {
        off1[s] = g_off[p * 8 + s];
        off2[s] = g_off[16 + p * 8 + s];
    }
    RYC ry[4];   // 0:1a plain, 1:1b plain, 2:2b fused, 3:l2a fused
#pragma unroll
    for (int m = 0; m < 4; m++) {
        float c0 = g_ryf[m * 8 + 0], s0 = g_ryf[m * 8 + 1];
        float c1 = g_ryf[m * 8 + 2], s1 = g_ryf[m * 8 + 3];
        float c2 = g_ryf[m * 8 + 4], s2 = g_ryf[m * 8 + 5];
        float c3 = g_ryf[m * 8 + 6], s3 = g_ryf[m * 8 + 7];
        float s0p = p ? s0 : -s0;
        if (m >= 2) {
            ry[m].D0 = PACK2(c0, s0p); ry[m].D1 = PACK2(s0p, c0);
        } else {
            ry[m].D0 = PACK2(c0, c0);  ry[m].D1 = PACK2(s0p, s0p);
        }
        ry[m].cc1 = PACK2(c1, c1); ry[m].ss1 = PACK2(s1, s1); ry[m].ns1 = PACK2(-s1, -s1);
        ry[m].cc2 = PACK2(c2, c2); ry[m].ss2 = PACK2(s2, s2); ry[m].ns2 = PACK2(-s2, -s2);
        ry[m].cc3 = PACK2(c3, c3); ry[m].sm3 = PACK2(-s3, s3);
    }
    ull d1r[12], d2r[12];
    {
        const ull* b = reinterpret_cast<const ull*>(g_d1) + p * 12;
        const ull* c = reinterpret_cast<const ull*>(g_d2m) + p * 12;
#pragma unroll
        for (int i = 0; i < 12; i++) { d1r[i] = b[i]; d2r[i] = c[i]; }
    }

    // h_ang holds PRE-HALVED angles throughout
    float h_ang[7];
#pragma unroll
    for (int k = 0; k < 7; k++) h_ang[k] = 0.5f * initial_t[e * 7 + k];

    const float4* inp = reinterpret_cast<const float4*>(inputs) + (size_t)e * SLEN;

    float hid[4];
#pragma unroll 1
    for (int t = 0; t < SLEN; t++) {
        float4 xv = inp[t];
        float x_ang[7];   // pre-halved
        x_ang[0] = 0.5f * xv.x; x_ang[1] = 0.5f * xv.y;
        x_ang[2] = 0.5f * xv.z; x_ang[3] = 0.5f * xv.w;
        float u0 = PI_F - xv.x, u1 = PI_F - xv.y, u2 = PI_F - xv.z, u3 = PI_F - xv.w;
        float hu1 = 0.5f * u1, hu2 = 0.5f * u2;
        x_ang[4] = u0 * hu1;
        x_ang[5] = hu1 * u2;
        x_ang[6] = hu2 * u3;
        if (t > 0) kan_fp(hid, s_kanp, s_kans, h_ang);
        qcell(h_ang, x_ang, d1r, d2r, off1, off2,
              ry[0], ry[1], ry[2], ry[3], p, sgnp, hid);
    }

    float o = cb2[0];
#pragma unroll 1
    for (int k = 0; k < 16; k++) {
        float a = cb1[k];
        a = fmaf(cw1[k * 4 + 0], hid[0], a);
        a = fmaf(cw1[k * 4 + 1], hid[1], a);
        a = fmaf(cw1[k * 4 + 2], hid[2], a);
        a = fmaf(cw1[k * 4 + 3], hid[3], a);
        o = fmaf(cw2[k], fmaxf(a, 0.0f), o);
    }
    if (p == 0) out[e] = o;
}

extern "C" void kernel_launch(void* const* d_in, const int* in_sizes, int n_in,
                              void* d_out, int out_size) {
    const float* inputs    = (const float*)d_in[0];
    const float* initial_t = (const float*)d_in[1];
    const float* p1        = (const float*)d_in[2];
    const float* p2        = (const float*)d_in[3];
    const float* base_w    = (const float*)d_in[4];
    const float* spline_w  = (const float*)d_in[5];
    const float* cw1       = (const float*)d_in[6];
    const float* cb1       = (const float*)d_in[7];
    const float* cw2       = (const float*)d_in[8];
    const float* cb2       = (const float*)d_in[9];

    setup_kernel<<<1, 32>>>(p1, p2, base_w, spline_w);
    qrnn_kernel<<<(BATCH * 2) / 128, 128>>>(inputs, initial_t,
                                            cw1, cb1, cw2, cb2, (float*)d_out);
}